// round 13
// baseline (speedup 1.0000x reference)
#include <cuda_runtime.h>
#include <cuda_bf16.h>
#include <cuda_fp16.h>
#include <math.h>
#include <stdint.h>

#define Bn 8
#define Dc 6
#define NC 48
#define Hn 256
#define Wn 256
#define HW (Hn*Wn)
#define H2n 128
#define HW2 (H2n*H2n)

// ---------------- scratch ----------------
__device__ __half g_h1 [Bn*258*258*NC];          // NHWC fp16
__device__ float g_E  [Bn*HW];
__device__ __half g_h2 [Bn*NC*HW];               // NHWC fp16
__device__ float g_ch [Bn*HW2];
__device__ float g_z  [Bn*NC*HW2];
__device__ float g_hcm[Bn*NC*130*130];
__device__ float g_xm [Bn*Dc*HW2];
__device__ float g_w5 [25*NC];
__device__ uint32_t g_bfrag[9*3*6*32*2];         // B fragments [tap][kc][nt][lane][2]
__device__ float g_red[276];
__device__ float g_sb [384];

__device__ const int c_dx[8] = {0,1,1,1,0,-1,-1,-1};
__device__ const int c_dy[8] = {1,1,0,-1,-1,-1,0,1};

// ---- streams/events created at program init ----
struct HXStreams {
    cudaStream_t s2, s3;
    cudaEvent_t e1, e2, e3, e4;
    HXStreams() {
        cudaStreamCreateWithFlags(&s2, cudaStreamNonBlocking);
        cudaStreamCreateWithFlags(&s3, cudaStreamNonBlocking);
        cudaEventCreateWithFlags(&e1, cudaEventDisableTiming);
        cudaEventCreateWithFlags(&e2, cudaEventDisableTiming);
        cudaEventCreateWithFlags(&e3, cudaEventDisableTiming);
        cudaEventCreateWithFlags(&e4, cudaEventDisableTiming);
    }
};
static HXStreams g_hx;

__device__ __forceinline__ float ftanh(float x) {
    x = fminf(fmaxf(x, -15.f), 15.f);
    float e = __expf(2.f*x);
    return __fdividef(e - 1.f, e + 1.f);
}
__device__ __forceinline__ float fsig(float x) {
    return __fdividef(1.f, 1.f + __expf(-x));
}

// ---- packed f32x2 ----
__device__ __forceinline__ unsigned long long pack2(float a, float b) {
    unsigned long long r;
    asm("mov.b64 %0, {%1, %2};" : "=l"(r) : "f"(a), "f"(b));
    return r;
}
__device__ __forceinline__ void ffma2(unsigned long long &d, unsigned long long a,
                                      unsigned long long b) {
    asm("fma.rn.f32x2 %0, %1, %2, %0;" : "+l"(d) : "l"(a), "l"(b));
}
__device__ __forceinline__ float2 unpack2(unsigned long long v) {
    float2 f;
    asm("mov.b64 {%0, %1}, %2;" : "=f"(f.x), "=f"(f.y) : "l"(v));
    return f;
}

// ---- warp mma + ldmatrix ----
__device__ __forceinline__ void mma16816(float* d, const uint32_t* a, uint32_t b0, uint32_t b1) {
    asm volatile("mma.sync.aligned.m16n8k16.row.col.f32.f16.f16.f32 "
        "{%0,%1,%2,%3}, {%4,%5,%6,%7}, {%8,%9}, {%0,%1,%2,%3};"
        : "+f"(d[0]), "+f"(d[1]), "+f"(d[2]), "+f"(d[3])
        : "r"(a[0]), "r"(a[1]), "r"(a[2]), "r"(a[3]), "r"(b0), "r"(b1));
}
__device__ __forceinline__ void ldsm_x4(uint32_t* r, uint32_t addr) {
    asm volatile("ldmatrix.sync.aligned.m8n8.x4.shared.b16 {%0,%1,%2,%3}, [%4];"
        : "=r"(r[0]), "=r"(r[1]), "=r"(r[2]), "=r"(r[3]) : "r"(addr));
}
__device__ __forceinline__ uint32_t smem_u32(const void* p) {
    uint32_t a;
    asm("{ .reg .u64 t; cvta.to.shared.u64 t, %1; cvt.u32.u64 %0, t; }" : "=r"(a) : "l"(p));
    return a;
}

// smem layout of k_hmma_mdc1 (dynamic): A staging + reduction only (B frags via L1)
#define SM_IN  0
#define SM_RED 43680
#define SMEM_TOT (SM_RED + 384)

// ---------------- tiny kernels ----------------
__global__ void k_zero(float* red) { if (threadIdx.x < 276) red[threadIdx.x] = 0.f; }

__global__ void k_mom6(const float* __restrict__ x, float* __restrict__ out, int hw) {
    float S[6] = {0,0,0,0,0,0};
    float P[21];
    #pragma unroll
    for (int i = 0; i < 21; i++) P[i] = 0.f;
    int total = Bn*hw;
    for (int t = blockIdx.x*blockDim.x + threadIdx.x; t < total; t += gridDim.x*blockDim.x) {
        int b = t / hw, i = t - b*hw;
        const float* p = x + (long)b*6*hw + i;
        float v[6];
        #pragma unroll
        for (int d = 0; d < 6; d++) v[d] = p[(long)d*hw];
        int idx = 0;
        #pragma unroll
        for (int d = 0; d < 6; d++) {
            S[d] += v[d];
            #pragma unroll
            for (int e = d; e < 6; e++) { P[idx] += v[d]*v[e]; idx++; }
        }
    }
    #pragma unroll
    for (int o = 16; o > 0; o >>= 1) {
        #pragma unroll
        for (int d = 0; d < 6; d++)  S[d] += __shfl_down_sync(0xffffffffu, S[d], o);
        #pragma unroll
        for (int i = 0; i < 21; i++) P[i] += __shfl_down_sync(0xffffffffu, P[i], o);
    }
    if ((threadIdx.x & 31) == 0) {
        #pragma unroll
        for (int d = 0; d < 6; d++)  atomicAdd(&out[d], S[d]);
        #pragma unroll
        for (int i = 0; i < 21; i++) atomicAdd(&out[6+i], P[i]);
    }
}

__global__ void k_sb6(const float* __restrict__ mom, const float* __restrict__ w1,
                      const float* __restrict__ g, const float* __restrict__ bt,
                      float* __restrict__ sb, float invN) {
    int c = threadIdx.x;
    if (c >= NC) return;
    float m = 0.f;
    #pragma unroll
    for (int d = 0; d < 6; d++) m += w1[c*6+d]*mom[d];
    m *= invN;
    float q = 0.f; int idx = 0;
    #pragma unroll
    for (int d = 0; d < 6; d++)
        #pragma unroll
        for (int e = d; e < 6; e++) {
            float coef = (d == e) ? 1.f : 2.f;
            q += coef * w1[c*6+d]*w1[c*6+e]*mom[6+idx];
            idx++;
        }
    q *= invN;
    float var = q - m*m;
    float sc = g[c]*rsqrtf(var + 1e-5f);
    sb[c] = sc; sb[NC+c] = bt[c] - m*sc;
}

__global__ void k_bnsb(const float* __restrict__ sums, const float* __restrict__ g,
                       const float* __restrict__ bt, float* __restrict__ sb, float invN) {
    int c = threadIdx.x;
    if (c >= NC) return;
    float m = sums[c]*invN;
    float var = sums[NC+c]*invN - m*m;
    float sc = g[c]*rsqrtf(var + 1e-5f);
    sb[c] = sc; sb[NC+c] = bt[c] - m*sc;
}

__global__ void k_env(const float* __restrict__ x, const float* __restrict__ w1,
                      const float* __restrict__ w2, const float* __restrict__ sb,
                      float* __restrict__ E) {
    __shared__ float s_w1[288], s_w2[48], s_s[48], s_b[48];
    int t = threadIdx.x;
    for (int i = t; i < 288; i += 256) s_w1[i] = w1[i];
    if (t < 48) { s_w2[t] = w2[t]; s_s[t] = sb[t]; s_b[t] = sb[48+t]; }
    __syncthreads();
    int idx = blockIdx.x*256 + t;
    int b = idx >> 16, pix = idx & 65535;
    const float* xp = x + (long)b*6*HW + pix;
    float v[6];
    #pragma unroll
    for (int d = 0; d < 6; d++) v[d] = xp[(long)d*HW];
    float e = 0.f;
    #pragma unroll 4
    for (int c = 0; c < 48; c++) {
        float y = s_w1[c*6]*v[0];
        #pragma unroll
        for (int d = 1; d < 6; d++) y = fmaf(s_w1[c*6+d], v[d], y);
        e = fmaf(s_w2[c], ftanh(fmaf(s_s[c], y, s_b[c])), e);
    }
    E[idx] = e;
}

__global__ void k_w5(const float* __restrict__ md_ct, float* __restrict__ W5) {
    int oc = threadIdx.x;
    if (oc >= 48) return;
    float w5[25];
    #pragma unroll
    for (int i = 0; i < 25; i++) w5[i] = 0.f;
    for (int k = 0; k < 8; k++)
        for (int ky = 0; ky < 3; ky++)
            for (int kx = 0; kx < 3; kx++) {
                int u = ky - 2 + c_dy[k] + 3;
                int v = kx - 2 - c_dx[k] + 3;
                w5[u*5+v] += md_ct[oc*90 + (k+2)*9 + ky*3 + kx];
            }
    for (int i = 0; i < 25; i++) W5[i*48 + oc] = w5[i];
}

// md_c1 weights -> fp16 B fragments in mma register order
__global__ void k_wb(const float* __restrict__ md_c1, uint32_t* __restrict__ bfrag) {
    int i = blockIdx.x*256 + threadIdx.x;
    if (i >= 9*3*6*32*2) return;
    int r    = i & 1;
    int lane = (i >> 1) & 31;
    int nt   = (i >> 6) % 6;
    int kc   = (i / (64*6)) % 3;
    int tap  = i / (64*6*3);
    int n  = nt*8 + (lane >> 2);
    int k0 = (lane & 3)*2 + r*8;
    float w0 = md_c1[((n*48) + kc*16 + k0    )*9 + tap];
    float w1 = md_c1[((n*48) + kc*16 + k0 + 1)*9 + tap];
    __half2 pk;
    pk.x = __float2half_rn(w0);
    pk.y = __float2half_rn(w1);
    bfrag[i] = *(uint32_t*)&pk;
}

__device__ __forceinline__ void store_h2(__half* h1, long base, float v0, float v1) {
    __half2 p;
    p.x = __float2half_rn(v0);
    p.y = __float2half_rn(v1);
    *(uint32_t*)(h1 + base) = *(uint32_t*)&p;
}

// md_ct interior (FFMA2), outputs NHWC fp16
__global__ void __launch_bounds__(256, 2)
k_mdct(const float* __restrict__ x, const float* __restrict__ E,
       const float* __restrict__ W5, const float* __restrict__ md_ct,
       __half* __restrict__ h1) {
    __shared__ float sE[36*36];
    __shared__ float sx[2][34*34];
    __shared__ alignas(16) float s_w5[25*16];
    __shared__ alignas(16) float s_w3[2*9*16];
    int tid = threadIdx.x;
    int oc_base = blockIdx.x * 16;
    int b = blockIdx.z;
    int tX = blockIdx.y & 7, tY = blockIdx.y >> 3;
    int p0 = 2 + tY*32, q0 = 2 + tX*32;

    for (int i = tid; i < 25*16; i += 256) {
        int tap = i >> 4, o = i & 15;
        s_w5[i] = W5[tap*48 + oc_base + o];
    }
    for (int i = tid; i < 288; i += 256) {
        int o = i & 15, rest = i >> 4;
        s_w3[i] = md_ct[(oc_base + o)*90 + rest];
    }
    for (int i = tid; i < 1296; i += 256) {
        int lr = i / 36, lc = i - lr*36;
        int gy = (p0 - 3 + lr) & 255, gx = (q0 - 3 + lc) & 255;
        sE[i] = E[b*HW + (gy << 8) + gx];
    }
    #pragma unroll
    for (int ch = 0; ch < 2; ch++)
        for (int i = tid; i < 1156; i += 256) {
            int lr = i / 34, lc = i - lr*34;
            int gy = p0 - 2 + lr, gx = q0 - 2 + lc;
            float v = 0.f;
            if (gy < 256 && gx < 256) v = x[((long)b*6 + ch)*HW + (gy << 8) + gx];
            sx[ch][i] = v;
        }
    __syncthreads();

    int tx = tid & 31, ty = tid >> 5;
    unsigned long long acc2[4][8];
    #pragma unroll
    for (int p = 0; p < 4; p++)
        #pragma unroll
        for (int j = 0; j < 8; j++) acc2[p][j] = 0ull;

    #pragma unroll
    for (int u = 0; u < 5; u++) {
        float v[4][5];
        #pragma unroll
        for (int p = 0; p < 4; p++) {
            int base = (ty + 8*p + u)*36 + tx;
            #pragma unroll
            for (int j = 0; j < 5; j++) v[p][j] = sE[base + j];
        }
        #pragma unroll
        for (int vv = 0; vv < 5; vv++) {
            unsigned long long v2[4];
            #pragma unroll
            for (int p = 0; p < 4; p++) v2[p] = pack2(v[p][vv], v[p][vv]);
            const float4* w4 = (const float4*)&s_w5[(u*5 + vv)*16];
            #pragma unroll
            for (int q = 0; q < 4; q++) {
                float4 t4 = w4[q];
                unsigned long long wA = pack2(t4.x, t4.y), wB = pack2(t4.z, t4.w);
                #pragma unroll
                for (int p = 0; p < 4; p++) {
                    ffma2(acc2[p][q*2],   v2[p], wA);
                    ffma2(acc2[p][q*2+1], v2[p], wB);
                }
            }
        }
    }
    #pragma unroll
    for (int ch = 0; ch < 2; ch++)
        #pragma unroll
        for (int ky = 0; ky < 3; ky++) {
            float v[4][3];
            #pragma unroll
            for (int p = 0; p < 4; p++) {
                int base = (ty + 8*p + ky)*34 + tx;
                v[p][0] = sx[ch][base]; v[p][1] = sx[ch][base+1]; v[p][2] = sx[ch][base+2];
            }
            #pragma unroll
            for (int kx = 0; kx < 3; kx++) {
                unsigned long long v2[4];
                #pragma unroll
                for (int p = 0; p < 4; p++) v2[p] = pack2(v[p][kx], v[p][kx]);
                const float4* w4 = (const float4*)&s_w3[(ch*9 + ky*3 + kx)*16];
                #pragma unroll
                for (int q = 0; q < 4; q++) {
                    float4 t4 = w4[q];
                    unsigned long long wA = pack2(t4.x, t4.y), wB = pack2(t4.z, t4.w);
                    #pragma unroll
                    for (int p = 0; p < 4; p++) {
                        ffma2(acc2[p][q*2],   v2[p], wA);
                        ffma2(acc2[p][q*2+1], v2[p], wB);
                    }
                }
            }
        }

    #pragma unroll
    for (int p = 0; p < 4; p++) {
        int pp = p0 + ty + 8*p, qq = q0 + tx;
        if (pp <= 255 && qq <= 255) {
            long base = ((long)(b*258 + pp)*258 + qq)*48 + oc_base;
            #pragma unroll
            for (int j = 0; j < 8; j++) {
                float2 f = unpack2(acc2[p][j]);
                store_h2(h1, base + 2*j, ftanh(f.x), ftanh(f.y));
            }
        }
    }
}

// md_ct boundary
__global__ void k_mdct_edge(const float* __restrict__ x, const float* __restrict__ E,
                            const float* __restrict__ md_ct, __half* __restrict__ h1) {
    __shared__ float s_w[4320];
    int tid = threadIdx.x;
    for (int i = tid; i < 4320; i += 256) {
        int oc = i % 48, rest = i / 48;
        s_w[rest*48 + oc] = md_ct[oc*90 + rest];
    }
    __syncthreads();
    int idx = blockIdx.x*256 + tid;
    int b = blockIdx.y;
    int p, q;
    if (idx < 1032) { int r = idx/258; p = (r < 2) ? r : 254 + r; q = idx - r*258; }
    else { int j = idx - 1032; int c = j/254; q = (c < 2) ? c : 254 + c; p = 2 + (j - c*254); }
    float acc[48];
    #pragma unroll
    for (int o = 0; o < 48; o++) acc[o] = 0.f;
    for (int ch = 0; ch < 10; ch++)
        for (int ky = 0; ky < 3; ky++)
            for (int kx = 0; kx < 3; kx++) {
                int y = p - 2 + ky, xx = q - 2 + kx;
                if ((unsigned)y < 256u && (unsigned)xx < 256u) {
                    float v;
                    if (ch < 2) v = x[((long)b*6 + ch)*HW + (y << 8) + xx];
                    else {
                        int k = ch - 2;
                        v = E[b*HW + (((y + c_dy[k]) & 255) << 8) + ((xx - c_dx[k]) & 255)];
                    }
                    const float* wr = &s_w[(ch*9 + ky*3 + kx)*48];
                    #pragma unroll
                    for (int o = 0; o < 48; o++) acc[o] = fmaf(v, wr[o], acc[o]);
                }
            }
    long base = ((long)(b*258 + p)*258 + q)*48;
    #pragma unroll
    for (int o = 0; o < 48; o += 2)
        store_h2(h1, base + o, ftanh(acc[o]), ftanh(acc[o+1]));
}

// ---------------- md_c1 via warp fp16 mma (ldmatrix A, B frags from L1) ----------------
__global__ void __launch_bounds__(256, 3)
k_hmma_mdc1(const __half* __restrict__ h1, const uint32_t* __restrict__ bfrag,
            __half* __restrict__ h2, float* __restrict__ red) {
    extern __shared__ char smem[];
    uint32_t* sA  = (uint32_t*)(smem + SM_IN);
    float* s_red  = (float*)(smem + SM_RED);
    uint32_t sA_addr = smem_u32(smem) + SM_IN;

    int tid = threadIdx.x, wid = tid >> 5, lane = tid & 31;
    int wm = wid >> 1, wn = wid & 1;
    int g = lane >> 2, tg = lane & 3;
    int m0 = wm * 32;
    uint32_t roff = (uint32_t)(((lane & 15)*28 + (lane >> 4)*4) * 4);
    const uint2* bf = (const uint2*)bfrag + lane;

    if (tid < 96) s_red[tid] = 0.f;

    for (int t = 0; t < 4; t++) {
        int gt = blockIdx.x*4 + t;
        int hf = gt & 1, p = (gt >> 1) & 255, b = gt >> 9;
        int q0 = hf << 7;

        __syncthreads();
        const uint4* srcA = (const uint4*)(h1 + ((long)(b*258 + p)*258 + q0)*48);
        uint4* dstA = (uint4*)sA;
        for (int i = tid; i < 3*130*6; i += 256) {
            int px = i / 6, w4 = i - px*6;
            int ky = px / 130, lp = px - ky*130;
            dstA[px*7 + w4] = srcA[(long)ky*(258*6) + lp*6 + w4];
        }
        __syncthreads();

        float acc[2][3][4];
        #pragma unroll
        for (int mt = 0; mt < 2; mt++)
            #pragma unroll
            for (int nt = 0; nt < 3; nt++)
                #pragma unroll
                for (int r = 0; r < 4; r++) acc[mt][nt][r] = 0.f;

        #pragma unroll 1
        for (int tap = 0; tap < 9; tap++) {
            int ky = tap/3, kx = tap - ky*3;
            int rowbase = ky*130 + m0 + kx;
            #pragma unroll
            for (int kc = 0; kc < 3; kc++) {
                const uint2* bp = bf + ((tap*3 + kc)*6 + wn*3)*32;
                uint2 b0 = __ldg(bp);
                uint2 b1 = __ldg(bp + 32);
                uint2 b2 = __ldg(bp + 64);
                uint32_t ah[2][4];
                #pragma unroll
                for (int mt = 0; mt < 2; mt++) {
                    uint32_t addr = sA_addr + (uint32_t)((rowbase + mt*16)*112 + kc*32) + roff;
                    ldsm_x4(ah[mt], addr);
                }
                #pragma unroll
                for (int mt = 0; mt < 2; mt++) {
                    mma16816(acc[mt][0], ah[mt], b0.x, b0.y);
                    mma16816(acc[mt][1], ah[mt], b1.x, b1.y);
                    mma16816(acc[mt][2], ah[mt], b2.x, b2.y);
                }
            }
        }

        float csum[3][2], csq[3][2];
        #pragma unroll
        for (int ntl = 0; ntl < 3; ntl++) { csum[ntl][0]=0.f; csum[ntl][1]=0.f; csq[ntl][0]=0.f; csq[ntl][1]=0.f; }
        #pragma unroll
        for (int mt = 0; mt < 2; mt++) {
            int pr0 = q0 + m0 + mt*16 + g;
            __half* o0 = h2 + ((long)((b*256 + p)*256) + pr0)*48 + wn*24;
            __half* o1 = o0 + 8*48;
            #pragma unroll
            for (int ntl = 0; ntl < 3; ntl++) {
                float v0 = ftanh(acc[mt][ntl][0]);
                float v1 = ftanh(acc[mt][ntl][1]);
                float v2 = ftanh(acc[mt][ntl][2]);
                float v3 = ftanh(acc[mt][ntl][3]);
                int co = ntl*8 + tg*2;
                *(__half2*)(o0 + co) = __floats2half2_rn(v0, v1);
                *(__half2*)(o1 + co) = __floats2half2_rn(v2, v3);
                csum[ntl][0] += v0 + v2; csum[ntl][1] += v1 + v3;
                csq[ntl][0]  += v0*v0 + v2*v2; csq[ntl][1] += v1*v1 + v3*v3;
            }
        }
        #pragma unroll
        for (int ntl = 0; ntl < 3; ntl++)
            #pragma unroll
            for (int c2 = 0; c2 < 2; c2++) {
                float s = csum[ntl][c2], q = csq[ntl][c2];
                #pragma unroll
                for (int o = 16; o >= 4; o >>= 1) {
                    s += __shfl_down_sync(0xffffffffu, s, o);
                    q += __shfl_down_sync(0xffffffffu, q, o);
                }
                if (g == 0) {
                    int col = wn*24 + ntl*8 + tg*2 + c2;
                    atomicAdd(&s_red[col], s);
                    atomicAdd(&s_red[48 + col], q);
                }
            }
    }
    __syncthreads();
    for (int i = tid; i < 96; i += 256) atomicAdd(&red[i], s_red[i]);
}

// ---------------- direct 3x3 conv (FFMA2, double-buffered tiles) ----------------
template<int CIN_G, int OCB, int PAD, bool DOTANH, bool SAFE, bool PREBN>
__global__ void __launch_bounds__(256, 2)
k_conv3(const float* __restrict__ in, const float* __restrict__ wgt,
        const float* __restrict__ sbp, float* __restrict__ out,
        int H_in, int W_in, int H_out, int W_out, int C_in, int C_out, int tilesX) {
    __shared__ float s_tile[2][34*34];
    __shared__ alignas(16) float s_w[CIN_G*9*OCB];
    __shared__ float s_sc[CIN_G], s_bi[CIN_G];

    int tid = threadIdx.x;
    int oc_base = blockIdx.x * OCB;
    int groups = C_in / CIN_G;
    int oc_per_group = C_out / groups;
    int ic_base = (oc_base / oc_per_group) * CIN_G;

    for (int i = tid; i < CIN_G*9*OCB; i += 256) {
        int o = i % OCB, rest = i / OCB;
        s_w[i] = wgt[(long)(oc_base + o)*(CIN_G*9) + rest];
    }
    if (PREBN && tid < CIN_G) { s_sc[tid] = sbp[ic_base + tid]; s_bi[tid] = sbp[48 + ic_base + tid]; }

    int tX = blockIdx.y % tilesX, tY = blockIdx.y / tilesX;
    int ox0 = tX*32, oy0 = tY*32;
    int tx = tid & 31, ty = tid >> 5;

    int off[5]; bool vld[5];
    #pragma unroll
    for (int s = 0; s < 5; s++) {
        int j = tid + s*256;
        int ly = j / 34, lx = j - ly*34;
        int gy = oy0 - PAD + ly, gx = ox0 - PAD + lx;
        bool v = (j < 1156);
        if (SAFE) v = v && ((unsigned)gy < (unsigned)H_in) && ((unsigned)gx < (unsigned)W_in);
        vld[s] = v;
        off[s] = gy*W_in + gx;
    }

    const float* inb = in + ((long)blockIdx.z * C_in + ic_base) * H_in * W_in;
    float r[5];
    #pragma unroll
    for (int s = 0; s < 5; s++) r[s] = vld[s] ? __ldg(inb + off[s]) : 0.f;

    unsigned long long acc2[4][OCB/2];
    #pragma unroll
    for (int p = 0; p < 4; p++)
        #pragma unroll
        for (int j = 0; j < OCB/2; j++) acc2[p][j] = 0ull;

    // stage ic=0 into buffer 0 (PREBN applies for ic 0); need s_sc ready -> but
    // s_sc written by this block's threads above; safe because each thread reads
    // only after __syncthreads below?  NO: PREBN uses s_sc[0] before sync.
    // Avoid: stage raw, apply PREBN via registers loaded from gmem for ic0.
    {
        float sc = 0.f, bi = 0.f;
        if (PREBN) { sc = sbp[ic_base]; bi = sbp[48 + ic_base]; }
        #pragma unroll
        for (int s = 0; s < 5; s++) {
            int j = tid + s*256;
            if (j < 1156) {
                float v = r[s];
                if (PREBN) v = ftanh(fmaf(sc, v, bi));
                s_tile[0][j] = v;
            }
        }
    }
    if (CIN_G > 1) {
        const float* src = inb + (long)H_in*W_in;
        #pragma unroll
        for (int s = 0; s < 5; s++) r[s] = vld[s] ? __ldg(src + off[s]) : 0.f;
    }
    __syncthreads();

    #pragma unroll 1
    for (int ic = 0; ic < CIN_G; ic++) {
        int cur = ic & 1;
        if (ic + 1 < CIN_G) {
            float sc = 0.f, bi = 0.f;
            if (PREBN) { sc = s_sc[ic+1]; bi = s_bi[ic+1]; }
            #pragma unroll
            for (int s = 0; s < 5; s++) {
                int j = tid + s*256;
                if (j < 1156) {
                    float v = r[s];
                    if (PREBN) v = ftanh(fmaf(sc, v, bi));
                    s_tile[cur ^ 1][j] = v;
                }
            }
            if (ic + 2 < CIN_G) {
                const float* src = inb + (long)(ic+2)*H_in*W_in;
                #pragma unroll
                for (int s = 0; s < 5; s++) r[s] = vld[s] ? __ldg(src + off[s]) : 0.f;
            }
        }
        const float* wic = &s_w[ic*9*OCB];
        const float* tile = s_tile[cur];
        #pragma unroll
        for (int ky = 0; ky < 3; ky++) {
            float v[4][3];
            #pragma unroll
            for (int p = 0; p < 4; p++) {
                int base = (ty + 8*p + ky)*34 + tx;
                v[p][0] = tile[base]; v[p][1] = tile[base+1]; v[p][2] = tile[base+2];
            }
            #pragma unroll
            for (int kx = 0; kx < 3; kx++) {
                unsigned long long v2[4];
                #pragma unroll
                for (int p = 0; p < 4; p++) v2[p] = pack2(v[p][kx], v[p][kx]);
                if (OCB % 4 == 0) {
                    const float4* w4 = (const float4*)&wic[(ky*3 + kx)*OCB];
                    #pragma unroll
                    for (int q = 0; q < OCB/4; q++) {
                        float4 t4 = w4[q];
                        unsigned long long wA = pack2(t4.x, t4.y), wB = pack2(t4.z, t4.w);
                        #pragma unroll
                        for (int p = 0; p < 4; p++) {
                            ffma2(acc2[p][q*2],   v2[p], wA);
                            ffma2(acc2[p][q*2+1], v2[p], wB);
                        }
                    }
                } else {
                    #pragma unroll
                    for (int j = 0; j < OCB/2; j++) {
                        unsigned long long ww =
                            *(const unsigned long long*)&wic[(ky*3 + kx)*OCB + 2*j];
                        #pragma unroll
                        for (int p = 0; p < 4; p++) ffma2(acc2[p][j], v2[p], ww);
                    }
                }
            }
        }
        __syncthreads();
    }

    #pragma unroll
    for (int p = 0; p < 4; p++) {
        int oy = oy0 + ty + 8*p, ox = ox0 + tx;
        bool ok = (oy < H_out) && (ox < W_out);
        float* op = out + (((long)blockIdx.z*C_out + oc_base)*H_out + oy)*W_out + ox;
        long cs = (long)H_out*W_out;
        #pragma unroll
        for (int j = 0; j < OCB/2; j++) {
            float2 f = unpack2(acc2[p][j]);
            float v0 = DOTANH ? ftanh(f.x) : f.x;
            float v1 = DOTANH ? ftanh(f.y) : f.y;
            if (ok) { op[(2*j)*cs] = v0; op[(2*j+1)*cs] = v1; }
        }
    }
}

// CHANGE (h2 NHWC fp16)
__global__ void k_change(const __half* __restrict__ h2, const float* __restrict__ sb,
                         const float* __restrict__ w2, float* __restrict__ ch) {
    __shared__ float s_s[48], s_b[48], s_w[192];
    int t = threadIdx.x;
    if (t < 48) { s_s[t] = sb[t]; s_b[t] = sb[48+t]; }
    if (t < 192) s_w[t] = w2[t];
    __syncthreads();
    int idx = blockIdx.x*256 + t;
    int b = idx >> 14, pix = idx & 16383;
    int i = pix >> 7, j = pix & 127;
    const __half2* p00 = (const __half2*)(h2 + ((long)((b*256 + 2*i)*256) + 2*j)*48);
    const __half2* p01 = p00 + 24;
    const __half2* p10 = p00 + 256*24;
    const __half2* p11 = p10 + 24;
    float a = 0.f;
    #pragma unroll 4
    for (int c2 = 0; c2 < 24; c2++) {
        float2 v0 = __half22float2(p00[c2]);
        float2 v1 = __half22float2(p01[c2]);
        float2 v2 = __half22float2(p10[c2]);
        float2 v3 = __half22float2(p11[c2]);
        int c = c2*2;
        float s0 = s_s[c], b0 = s_b[c], s1 = s_s[c+1], b1 = s_b[c+1];
        a = fmaf(ftanh(fmaf(s0, v0.x, b0)), s_w[c*4+0],     a);
        a = fmaf(ftanh(fmaf(s1, v0.y, b1)), s_w[(c+1)*4+0], a);
        a = fmaf(ftanh(fmaf(s0, v1.x, b0)), s_w[c*4+1],     a);
        a = fmaf(ftanh(fmaf(s1, v1.y, b1)), s_w[(c+1)*4+1], a);
        a = fmaf(ftanh(fmaf(s0, v2.x, b0)), s_w[c*4+2],     a);
        a = fmaf(ftanh(fmaf(s1, v2.y, b1)), s_w[(c+1)*4+2], a);
        a = fmaf(ftanh(fmaf(s0, v3.x, b0)), s_w[c*4+3],     a);
        a = fmaf(ftanh(fmaf(s1, v3.y, b1)), s_w[(c+1)*4+3], a);
    }
    ch[idx] = fsig(a);
}

// cm conv1 (2x2 s2 g3) — 2 outputs/thread via float4 loads, fused reduction
__global__ void k_cm1red(const float* __restrict__ x, const float* __restrict__ w,
                         float* __restrict__ z, float* __restrict__ red) {
    __shared__ float ss[8], sq[8];
    int tid = threadIdx.x;
    int idx = blockIdx.x*256 + tid;            // Bn*48*8192 units of 2 outputs
    int b = idx / (48*8192); int r = idx - b*48*8192;
    int oc = r >> 13; int unit = r & 8191;
    int i = unit >> 6, u = unit & 63;
    int g = oc >> 4;
    const float* xp = x + ((long)b*6 + 2*g)*HW + (2*i)*256 + 4*u;
    const float* wp = w + oc*8;
    float4 a0 = *(const float4*)xp;
    float4 a1 = *(const float4*)(xp + 256);
    float4 b0 = *(const float4*)(xp + HW);
    float4 b1 = *(const float4*)(xp + HW + 256);
    float o0 = wp[0]*a0.x + wp[1]*a0.y + wp[2]*a1.x + wp[3]*a1.y
             + wp[4]*b0.x + wp[5]*b0.y + wp[6]*b1.x + wp[7]*b1.y;
    float o1 = wp[0]*a0.z + wp[1]*a0.w + wp[2]*a1.z + wp[3]*a1.w
             + wp[4]*b0.z + wp[5]*b0.w + wp[6]*b1.z + wp[7]*b1.w;
    *(float2*)(z + (long)idx*2) = make_float2(o0, o1);
    float s = o0 + o1, q = o0*o0 + o1*o1;
    #pragma unroll
    for (int d = 16; d > 0; d >>= 1) {
        s += __shfl_down_sync(0xffffffffu, s, d);
        q += __shfl_down_sync(0xffffffffu, q, d);
    }
    int warp = tid >> 5, lane = tid & 31;
    if (lane == 0) { ss[warp] = s; sq[warp] = q; }
    __syncthreads();
    if (tid == 0) {
        float S = 0.f, Q = 0.f;
        #pragma unroll
        for (int w8 = 0; w8 < 8; w8++) { S += ss[w8]; Q += sq[w8]; }
        atomicAdd(&red[oc], S); atomicAdd(&red[48 + oc], Q);
    }
}

__global__ void k_final(const float* __restrict__ xm, const float* __restrict__ ch,
                        const float* __restrict__ w1, const float* __restrict__ w2,
                        const float* __restrict__ sb, float* __restrict__ out) {
    __shared__ float s_w1[288], s_w2[288], s_s[48], s_b[48];
    int t = threadIdx.x;
    for (int i = t; i < 288; i += 256) { s_w1[i] = w1[i]; s_w2[i] = w2[i]; }
    if (t < 48)  { s_s[t] = sb[t]; s_b[t] = sb[48+t]; }
    __syncthreads();
    int idx = blockIdx.x*256 + t;
    int b = idx >> 14, pix = idx & 16383;
    const float* xp = xm + ((long)b*6)*HW2 + pix;
    float v[6];
    #pragma unroll
    for (int d = 0; d < 6; d++) v[d] = xp[d*HW2];
    float born[6] = {0,0,0,0,0,0};
    #pragma unroll 4
    for (int c = 0; c < 48; c++) {
        float y = s_w1[c*6]*v[0];
        #pragma unroll
        for (int d = 1; d < 6; d++) y = fmaf(s_w1[c*6+d], v[d], y);
        float h = ftanh(fmaf(s_s[c], y, s_b[c]));
        #pragma unroll
        for (int d = 0; d < 6; d++) born[d] = fmaf(s_w2[d*48+c], h, born[d]);
    }
    float cc = ch[idx];
    #pragma unroll
    for (int d = 0; d < 6; d++) {
        float o = v[d]*(1.f - cc) + cc*born[d];
        if (d < 3) o = fsig(o);
        out[((long)b*6 + d)*HW2 + pix] = o;
    }
}

// ---------------- launch ----------------
extern "C" void kernel_launch(void* const* d_in, const int* in_sizes, int n_in,
                              void* d_out, int out_size) {
    const float* x     = (const float*)d_in[0];
    const float* ce_w1 = (const float*)d_in[1];
    const float* ce_g  = (const float*)d_in[2];
    const float* ce_b  = (const float*)d_in[3];
    const float* ce_w2 = (const float*)d_in[4];
    const float* md_ct = (const float*)d_in[5];
    const float* md_c1 = (const float*)d_in[6];
    const float* md_g  = (const float*)d_in[7];
    const float* md_b  = (const float*)d_in[8];
    const float* md_c2 = (const float*)d_in[9];
    const float* cm_w1 = (const float*)d_in[10];
    const float* cm_g  = (const float*)d_in[11];
    const float* cm_b  = (const float*)d_in[12];
    const float* cm_ct = (const float*)d_in[13];
    const float* cm_c2 = (const float*)d_in[14];
    const float* bo_w1 = (const float*)d_in[15];
    const float* bo_g  = (const float*)d_in[16];
    const float* bo_b  = (const float*)d_in[17];
    const float* bo_w2 = (const float*)d_in[18];

    float *E, *ch, *z, *hcm, *xm, *w5, *red, *sb;
    __half *h1, *h2;
    uint32_t *bfrag;
    cudaGetSymbolAddress((void**)&E,     g_E);
    cudaGetSymbolAddress((void**)&h1,    g_h1);
    cudaGetSymbolAddress((void**)&h2,    g_h2);
    cudaGetSymbolAddress((void**)&ch,    g_ch);
    cudaGetSymbolAddress((void**)&z,     g_z);
    cudaGetSymbolAddress((void**)&hcm,   g_hcm);
    cudaGetSymbolAddress((void**)&xm,    g_xm);
    cudaGetSymbolAddress((void**)&w5,    g_w5);
    cudaGetSymbolAddress((void**)&red,   g_red);
    cudaGetSymbolAddress((void**)&sb,    g_sb);
    cudaGetSymbolAddress((void**)&bfrag, g_bfrag);

    cudaFuncSetAttribute(k_hmma_mdc1, cudaFuncAttributeMaxDynamicSharedMemorySize, SMEM_TOT);

    const float invN_full = 1.f/(float)(Bn*HW);
    const float invN_half = 1.f/(float)(Bn*HW2);

    k_zero<<<1, 512>>>(red);
    cudaEventRecord(g_hx.e1, 0);

    // ---- cell-merge chain on s2 ----
    cudaStreamWaitEvent(g_hx.s2, g_hx.e1, 0);
    k_cm1red<<<Bn*48*8192/256, 256, 0, g_hx.s2>>>(x, cm_w1, z, red + 138);
    k_bnsb<<<1, 64, 0, g_hx.s2>>>(red + 138, cm_g, cm_b, sb + 192, invN_half);
    k_conv3<16, 16, 2, true, true, true>
        <<<dim3(3, 25, Bn), 256, 0, g_hx.s2>>>(z, cm_ct, sb + 192, hcm,
                                               128, 128, 130, 130, 48, 48, 5);
    k_conv3<16, 2, 0, true, false, false>
        <<<dim3(3, 16, Bn), 256, 0, g_hx.s2>>>(hcm, cm_c2, nullptr, xm,
                                               130, 130, 128, 128, 48, 6, 4);
    k_mom6<<<592, 256, 0, g_hx.s2>>>(xm, red + 234, HW2);
    k_sb6 <<<1, 64, 0, g_hx.s2>>>(red + 234, bo_w1, bo_g, bo_b, sb + 288, invN_half);
    cudaEventRecord(g_hx.e2, g_hx.s2);

    // ---- md chain on default stream ----
    k_mom6<<<592, 256>>>(x, red + 0, HW);
    k_sb6 <<<1, 64>>>(red + 0, ce_w1, ce_g, ce_b, sb + 0, invN_full);
    k_w5<<<1, 64>>>(md_ct, w5);
    k_env <<<Bn*HW/256, 256>>>(x, ce_w1, ce_w2, sb + 0, E);
    cudaEventRecord(g_hx.e3, 0);

    // s3 branch: wb + boundary pixels, concurrent with k_mdct
    cudaStreamWaitEvent(g_hx.s3, g_hx.e3, 0);
    k_wb<<<41, 256, 0, g_hx.s3>>>(md_c1, bfrag);
    k_mdct_edge<<<dim3(8, Bn), 256, 0, g_hx.s3>>>(x, E, md_ct, h1);
    cudaEventRecord(g_hx.e4, g_hx.s3);

    k_mdct<<<dim3(3, 64, Bn), 256>>>(x, E, w5, md_ct, h1);
    cudaStreamWaitEvent(0, g_hx.e4, 0);
    k_hmma_mdc1<<<1024, 256, SMEM_TOT>>>(h1, bfrag, h2, red + 42);
    k_bnsb<<<1, 64>>>(red + 42, md_g, md_b, sb + 96, invN_full);
    k_change<<<Bn*HW2/256, 256>>>(h2, sb + 96, md_c2, ch);

    // ---- join, then final blend ----
    cudaStreamWaitEvent(0, g_hx.e2, 0);
    k_final<<<Bn*HW2/256, 256>>>(xm, ch, bo_w1, bo_w2, sb + 288, (float*)d_out);
}

// round 14
// speedup vs baseline: 1.3629x; 1.3629x over previous
#include <cuda_runtime.h>
#include <cuda_bf16.h>
#include <cuda_fp16.h>
#include <math.h>
#include <stdint.h>

#define Bn 8
#define Dc 6
#define NC 48
#define Hn 256
#define Wn 256
#define HW (Hn*Wn)
#define H2n 128
#define HW2 (H2n*H2n)

// ---------------- scratch ----------------
__device__ __half g_h1 [Bn*258*258*NC];          // NHWC fp16
__device__ float g_E  [Bn*HW];
__device__ __half g_h2 [Bn*NC*HW];               // NHWC fp16
__device__ float g_ch [Bn*HW2];
__device__ float g_z  [Bn*NC*HW2];
__device__ float g_hcm[Bn*NC*130*130];
__device__ float g_xm [Bn*Dc*HW2];
__device__ float g_w5 [25*NC];
__device__ uint32_t g_bfrag[9*3*6*32*2];         // B fragments [tap][kc][nt][lane][2]
__device__ float g_red[276];
__device__ float g_sb [384];

__device__ const int c_dx[8] = {0,1,1,1,0,-1,-1,-1};
__device__ const int c_dy[8] = {1,1,0,-1,-1,-1,0,1};

// ---- streams/events created at program init ----
struct HXStreams {
    cudaStream_t s2;
    cudaEvent_t e1, e2;
    HXStreams() {
        cudaStreamCreateWithFlags(&s2, cudaStreamNonBlocking);
        cudaEventCreateWithFlags(&e1, cudaEventDisableTiming);
        cudaEventCreateWithFlags(&e2, cudaEventDisableTiming);
    }
};
static HXStreams g_hx;

__device__ __forceinline__ float ftanh(float x) {
    x = fminf(fmaxf(x, -15.f), 15.f);
    float e = __expf(2.f*x);
    return __fdividef(e - 1.f, e + 1.f);
}
__device__ __forceinline__ float fsig(float x) {
    return __fdividef(1.f, 1.f + __expf(-x));
}

// ---- packed f32x2 ----
__device__ __forceinline__ unsigned long long pack2(float a, float b) {
    unsigned long long r;
    asm("mov.b64 %0, {%1, %2};" : "=l"(r) : "f"(a), "f"(b));
    return r;
}
__device__ __forceinline__ void ffma2(unsigned long long &d, unsigned long long a,
                                      unsigned long long b) {
    asm("fma.rn.f32x2 %0, %1, %2, %0;" : "+l"(d) : "l"(a), "l"(b));
}
__device__ __forceinline__ float2 unpack2(unsigned long long v) {
    float2 f;
    asm("mov.b64 {%0, %1}, %2;" : "=f"(f.x), "=f"(f.y) : "l"(v));
    return f;
}

// ---- warp mma + ldmatrix ----
__device__ __forceinline__ void mma16816(float* d, const uint32_t* a, uint32_t b0, uint32_t b1) {
    asm volatile("mma.sync.aligned.m16n8k16.row.col.f32.f16.f16.f32 "
        "{%0,%1,%2,%3}, {%4,%5,%6,%7}, {%8,%9}, {%0,%1,%2,%3};"
        : "+f"(d[0]), "+f"(d[1]), "+f"(d[2]), "+f"(d[3])
        : "r"(a[0]), "r"(a[1]), "r"(a[2]), "r"(a[3]), "r"(b0), "r"(b1));
}
__device__ __forceinline__ void ldsm_x4(uint32_t* r, uint32_t addr) {
    asm volatile("ldmatrix.sync.aligned.m8n8.x4.shared.b16 {%0,%1,%2,%3}, [%4];"
        : "=r"(r[0]), "=r"(r[1]), "=r"(r[2]), "=r"(r[3]) : "r"(addr));
}
__device__ __forceinline__ uint32_t smem_u32(const void* p) {
    uint32_t a;
    asm("{ .reg .u64 t; cvta.to.shared.u64 t, %1; cvt.u32.u64 %0, t; }" : "=r"(a) : "l"(p));
    return a;
}

// smem layout of k_hmma_mdc1 (dynamic): A staging + reduction only (B frags via L1)
#define SM_IN  0
#define SM_RED 43680
#define SMEM_TOT (SM_RED + 384)

// ---------------- tiny kernels ----------------
__global__ void k_zero(float* red) { if (threadIdx.x < 276) red[threadIdx.x] = 0.f; }

__global__ void k_mom6(const float* __restrict__ x, float* __restrict__ out, int hw) {
    float S[6] = {0,0,0,0,0,0};
    float P[21];
    #pragma unroll
    for (int i = 0; i < 21; i++) P[i] = 0.f;
    int total = Bn*hw;
    for (int t = blockIdx.x*blockDim.x + threadIdx.x; t < total; t += gridDim.x*blockDim.x) {
        int b = t / hw, i = t - b*hw;
        const float* p = x + (long)b*6*hw + i;
        float v[6];
        #pragma unroll
        for (int d = 0; d < 6; d++) v[d] = p[(long)d*hw];
        int idx = 0;
        #pragma unroll
        for (int d = 0; d < 6; d++) {
            S[d] += v[d];
            #pragma unroll
            for (int e = d; e < 6; e++) { P[idx] += v[d]*v[e]; idx++; }
        }
    }
    #pragma unroll
    for (int o = 16; o > 0; o >>= 1) {
        #pragma unroll
        for (int d = 0; d < 6; d++)  S[d] += __shfl_down_sync(0xffffffffu, S[d], o);
        #pragma unroll
        for (int i = 0; i < 21; i++) P[i] += __shfl_down_sync(0xffffffffu, P[i], o);
    }
    if ((threadIdx.x & 31) == 0) {
        #pragma unroll
        for (int d = 0; d < 6; d++)  atomicAdd(&out[d], S[d]);
        #pragma unroll
        for (int i = 0; i < 21; i++) atomicAdd(&out[6+i], P[i]);
    }
}

__global__ void k_sb6(const float* __restrict__ mom, const float* __restrict__ w1,
                      const float* __restrict__ g, const float* __restrict__ bt,
                      float* __restrict__ sb, float invN) {
    int c = threadIdx.x;
    if (c >= NC) return;
    float m = 0.f;
    #pragma unroll
    for (int d = 0; d < 6; d++) m += w1[c*6+d]*mom[d];
    m *= invN;
    float q = 0.f; int idx = 0;
    #pragma unroll
    for (int d = 0; d < 6; d++)
        #pragma unroll
        for (int e = d; e < 6; e++) {
            float coef = (d == e) ? 1.f : 2.f;
            q += coef * w1[c*6+d]*w1[c*6+e]*mom[6+idx];
            idx++;
        }
    q *= invN;
    float var = q - m*m;
    float sc = g[c]*rsqrtf(var + 1e-5f);
    sb[c] = sc; sb[NC+c] = bt[c] - m*sc;
}

__global__ void k_bnsb(const float* __restrict__ sums, const float* __restrict__ g,
                       const float* __restrict__ bt, float* __restrict__ sb, float invN) {
    int c = threadIdx.x;
    if (c >= NC) return;
    float m = sums[c]*invN;
    float var = sums[NC+c]*invN - m*m;
    float sc = g[c]*rsqrtf(var + 1e-5f);
    sb[c] = sc; sb[NC+c] = bt[c] - m*sc;
}

__global__ void k_env(const float* __restrict__ x, const float* __restrict__ w1,
                      const float* __restrict__ w2, const float* __restrict__ sb,
                      float* __restrict__ E) {
    __shared__ float s_w1[288], s_w2[48], s_s[48], s_b[48];
    int t = threadIdx.x;
    for (int i = t; i < 288; i += 256) s_w1[i] = w1[i];
    if (t < 48) { s_w2[t] = w2[t]; s_s[t] = sb[t]; s_b[t] = sb[48+t]; }
    __syncthreads();
    int idx = blockIdx.x*256 + t;
    int b = idx >> 16, pix = idx & 65535;
    const float* xp = x + (long)b*6*HW + pix;
    float v[6];
    #pragma unroll
    for (int d = 0; d < 6; d++) v[d] = xp[(long)d*HW];
    float e = 0.f;
    #pragma unroll 4
    for (int c = 0; c < 48; c++) {
        float y = s_w1[c*6]*v[0];
        #pragma unroll
        for (int d = 1; d < 6; d++) y = fmaf(s_w1[c*6+d], v[d], y);
        e = fmaf(s_w2[c], ftanh(fmaf(s_s[c], y, s_b[c])), e);
    }
    E[idx] = e;
}

__global__ void k_w5(const float* __restrict__ md_ct, float* __restrict__ W5) {
    int oc = threadIdx.x;
    if (oc >= 48) return;
    float w5[25];
    #pragma unroll
    for (int i = 0; i < 25; i++) w5[i] = 0.f;
    for (int k = 0; k < 8; k++)
        for (int ky = 0; ky < 3; ky++)
            for (int kx = 0; kx < 3; kx++) {
                int u = ky - 2 + c_dy[k] + 3;
                int v = kx - 2 - c_dx[k] + 3;
                w5[u*5+v] += md_ct[oc*90 + (k+2)*9 + ky*3 + kx];
            }
    for (int i = 0; i < 25; i++) W5[i*48 + oc] = w5[i];
}

// md_c1 weights -> fp16 B fragments in mma register order
__global__ void k_wb(const float* __restrict__ md_c1, uint32_t* __restrict__ bfrag) {
    int i = blockIdx.x*256 + threadIdx.x;
    if (i >= 9*3*6*32*2) return;
    int r    = i & 1;
    int lane = (i >> 1) & 31;
    int nt   = (i >> 6) % 6;
    int kc   = (i / (64*6)) % 3;
    int tap  = i / (64*6*3);
    int n  = nt*8 + (lane >> 2);
    int k0 = (lane & 3)*2 + r*8;
    float w0 = md_c1[((n*48) + kc*16 + k0    )*9 + tap];
    float w1 = md_c1[((n*48) + kc*16 + k0 + 1)*9 + tap];
    __half2 pk;
    pk.x = __float2half_rn(w0);
    pk.y = __float2half_rn(w1);
    bfrag[i] = *(uint32_t*)&pk;
}

__device__ __forceinline__ void store_h2(__half* h1, long base, float v0, float v1) {
    __half2 p;
    p.x = __float2half_rn(v0);
    p.y = __float2half_rn(v1);
    *(uint32_t*)(h1 + base) = *(uint32_t*)&p;
}

// md_ct interior (FFMA2), outputs NHWC fp16
__global__ void __launch_bounds__(256, 2)
k_mdct(const float* __restrict__ x, const float* __restrict__ E,
       const float* __restrict__ W5, const float* __restrict__ md_ct,
       __half* __restrict__ h1) {
    __shared__ float sE[36*36];
    __shared__ float sx[2][34*34];
    __shared__ alignas(16) float s_w5[25*16];
    __shared__ alignas(16) float s_w3[2*9*16];
    int tid = threadIdx.x;
    int oc_base = blockIdx.x * 16;
    int b = blockIdx.z;
    int tX = blockIdx.y & 7, tY = blockIdx.y >> 3;
    int p0 = 2 + tY*32, q0 = 2 + tX*32;

    for (int i = tid; i < 25*16; i += 256) {
        int tap = i >> 4, o = i & 15;
        s_w5[i] = W5[tap*48 + oc_base + o];
    }
    for (int i = tid; i < 288; i += 256) {
        int o = i & 15, rest = i >> 4;
        s_w3[i] = md_ct[(oc_base + o)*90 + rest];
    }
    for (int i = tid; i < 1296; i += 256) {
        int lr = i / 36, lc = i - lr*36;
        int gy = (p0 - 3 + lr) & 255, gx = (q0 - 3 + lc) & 255;
        sE[i] = E[b*HW + (gy << 8) + gx];
    }
    #pragma unroll
    for (int ch = 0; ch < 2; ch++)
        for (int i = tid; i < 1156; i += 256) {
            int lr = i / 34, lc = i - lr*34;
            int gy = p0 - 2 + lr, gx = q0 - 2 + lc;
            float v = 0.f;
            if (gy < 256 && gx < 256) v = x[((long)b*6 + ch)*HW + (gy << 8) + gx];
            sx[ch][i] = v;
        }
    __syncthreads();

    int tx = tid & 31, ty = tid >> 5;
    unsigned long long acc2[4][8];
    #pragma unroll
    for (int p = 0; p < 4; p++)
        #pragma unroll
        for (int j = 0; j < 8; j++) acc2[p][j] = 0ull;

    #pragma unroll
    for (int u = 0; u < 5; u++) {
        float v[4][5];
        #pragma unroll
        for (int p = 0; p < 4; p++) {
            int base = (ty + 8*p + u)*36 + tx;
            #pragma unroll
            for (int j = 0; j < 5; j++) v[p][j] = sE[base + j];
        }
        #pragma unroll
        for (int vv = 0; vv < 5; vv++) {
            unsigned long long v2[4];
            #pragma unroll
            for (int p = 0; p < 4; p++) v2[p] = pack2(v[p][vv], v[p][vv]);
            const float4* w4 = (const float4*)&s_w5[(u*5 + vv)*16];
            #pragma unroll
            for (int q = 0; q < 4; q++) {
                float4 t4 = w4[q];
                unsigned long long wA = pack2(t4.x, t4.y), wB = pack2(t4.z, t4.w);
                #pragma unroll
                for (int p = 0; p < 4; p++) {
                    ffma2(acc2[p][q*2],   v2[p], wA);
                    ffma2(acc2[p][q*2+1], v2[p], wB);
                }
            }
        }
    }
    #pragma unroll
    for (int ch = 0; ch < 2; ch++)
        #pragma unroll
        for (int ky = 0; ky < 3; ky++) {
            float v[4][3];
            #pragma unroll
            for (int p = 0; p < 4; p++) {
                int base = (ty + 8*p + ky)*34 + tx;
                v[p][0] = sx[ch][base]; v[p][1] = sx[ch][base+1]; v[p][2] = sx[ch][base+2];
            }
            #pragma unroll
            for (int kx = 0; kx < 3; kx++) {
                unsigned long long v2[4];
                #pragma unroll
                for (int p = 0; p < 4; p++) v2[p] = pack2(v[p][kx], v[p][kx]);
                const float4* w4 = (const float4*)&s_w3[(ch*9 + ky*3 + kx)*16];
                #pragma unroll
                for (int q = 0; q < 4; q++) {
                    float4 t4 = w4[q];
                    unsigned long long wA = pack2(t4.x, t4.y), wB = pack2(t4.z, t4.w);
                    #pragma unroll
                    for (int p = 0; p < 4; p++) {
                        ffma2(acc2[p][q*2],   v2[p], wA);
                        ffma2(acc2[p][q*2+1], v2[p], wB);
                    }
                }
            }
        }

    #pragma unroll
    for (int p = 0; p < 4; p++) {
        int pp = p0 + ty + 8*p, qq = q0 + tx;
        if (pp <= 255 && qq <= 255) {
            long base = ((long)(b*258 + pp)*258 + qq)*48 + oc_base;
            #pragma unroll
            for (int j = 0; j < 8; j++) {
                float2 f = unpack2(acc2[p][j]);
                store_h2(h1, base + 2*j, ftanh(f.x), ftanh(f.y));
            }
        }
    }
}

// md_ct boundary
__global__ void k_mdct_edge(const float* __restrict__ x, const float* __restrict__ E,
                            const float* __restrict__ md_ct, __half* __restrict__ h1) {
    __shared__ float s_w[4320];
    int tid = threadIdx.x;
    for (int i = tid; i < 4320; i += 256) {
        int oc = i % 48, rest = i / 48;
        s_w[rest*48 + oc] = md_ct[oc*90 + rest];
    }
    __syncthreads();
    int idx = blockIdx.x*256 + tid;
    int b = blockIdx.y;
    int p, q;
    if (idx < 1032) { int r = idx/258; p = (r < 2) ? r : 254 + r; q = idx - r*258; }
    else { int j = idx - 1032; int c = j/254; q = (c < 2) ? c : 254 + c; p = 2 + (j - c*254); }
    float acc[48];
    #pragma unroll
    for (int o = 0; o < 48; o++) acc[o] = 0.f;
    for (int ch = 0; ch < 10; ch++)
        for (int ky = 0; ky < 3; ky++)
            for (int kx = 0; kx < 3; kx++) {
                int y = p - 2 + ky, xx = q - 2 + kx;
                if ((unsigned)y < 256u && (unsigned)xx < 256u) {
                    float v;
                    if (ch < 2) v = x[((long)b*6 + ch)*HW + (y << 8) + xx];
                    else {
                        int k = ch - 2;
                        v = E[b*HW + (((y + c_dy[k]) & 255) << 8) + ((xx - c_dx[k]) & 255)];
                    }
                    const float* wr = &s_w[(ch*9 + ky*3 + kx)*48];
                    #pragma unroll
                    for (int o = 0; o < 48; o++) acc[o] = fmaf(v, wr[o], acc[o]);
                }
            }
    long base = ((long)(b*258 + p)*258 + q)*48;
    #pragma unroll
    for (int o = 0; o < 48; o += 2)
        store_h2(h1, base + o, ftanh(acc[o]), ftanh(acc[o+1]));
}

// ---------------- md_c1 via warp fp16 mma (ldmatrix A, B frags from L1) ----------------
__global__ void __launch_bounds__(256, 3)
k_hmma_mdc1(const __half* __restrict__ h1, const uint32_t* __restrict__ bfrag,
            __half* __restrict__ h2, float* __restrict__ red) {
    extern __shared__ char smem[];
    uint32_t* sA  = (uint32_t*)(smem + SM_IN);
    float* s_red  = (float*)(smem + SM_RED);
    uint32_t sA_addr = smem_u32(smem) + SM_IN;

    int tid = threadIdx.x, wid = tid >> 5, lane = tid & 31;
    int wm = wid >> 1, wn = wid & 1;
    int g = lane >> 2, tg = lane & 3;
    int m0 = wm * 32;
    uint32_t roff = (uint32_t)(((lane & 15)*28 + (lane >> 4)*4) * 4);
    const uint2* bf = (const uint2*)bfrag + lane;

    if (tid < 96) s_red[tid] = 0.f;

    for (int t = 0; t < 4; t++) {
        int gt = blockIdx.x*4 + t;
        int hf = gt & 1, p = (gt >> 1) & 255, b = gt >> 9;
        int q0 = hf << 7;

        __syncthreads();
        const uint4* srcA = (const uint4*)(h1 + ((long)(b*258 + p)*258 + q0)*48);
        uint4* dstA = (uint4*)sA;
        for (int i = tid; i < 3*130*6; i += 256) {
            int px = i / 6, w4 = i - px*6;
            int ky = px / 130, lp = px - ky*130;
            dstA[px*7 + w4] = srcA[(long)ky*(258*6) + lp*6 + w4];
        }
        __syncthreads();

        float acc[2][3][4];
        #pragma unroll
        for (int mt = 0; mt < 2; mt++)
            #pragma unroll
            for (int nt = 0; nt < 3; nt++)
                #pragma unroll
                for (int r = 0; r < 4; r++) acc[mt][nt][r] = 0.f;

        #pragma unroll 1
        for (int tap = 0; tap < 9; tap++) {
            int ky = tap/3, kx = tap - ky*3;
            int rowbase = ky*130 + m0 + kx;
            #pragma unroll
            for (int kc = 0; kc < 3; kc++) {
                const uint2* bp = bf + ((tap*3 + kc)*6 + wn*3)*32;
                uint2 b0 = __ldg(bp);
                uint2 b1 = __ldg(bp + 32);
                uint2 b2 = __ldg(bp + 64);
                uint32_t ah[2][4];
                #pragma unroll
                for (int mt = 0; mt < 2; mt++) {
                    uint32_t addr = sA_addr + (uint32_t)((rowbase + mt*16)*112 + kc*32) + roff;
                    ldsm_x4(ah[mt], addr);
                }
                #pragma unroll
                for (int mt = 0; mt < 2; mt++) {
                    mma16816(acc[mt][0], ah[mt], b0.x, b0.y);
                    mma16816(acc[mt][1], ah[mt], b1.x, b1.y);
                    mma16816(acc[mt][2], ah[mt], b2.x, b2.y);
                }
            }
        }

        float csum[3][2], csq[3][2];
        #pragma unroll
        for (int ntl = 0; ntl < 3; ntl++) { csum[ntl][0]=0.f; csum[ntl][1]=0.f; csq[ntl][0]=0.f; csq[ntl][1]=0.f; }
        #pragma unroll
        for (int mt = 0; mt < 2; mt++) {
            int pr0 = q0 + m0 + mt*16 + g;
            __half* o0 = h2 + ((long)((b*256 + p)*256) + pr0)*48 + wn*24;
            __half* o1 = o0 + 8*48;
            #pragma unroll
            for (int ntl = 0; ntl < 3; ntl++) {
                float v0 = ftanh(acc[mt][ntl][0]);
                float v1 = ftanh(acc[mt][ntl][1]);
                float v2 = ftanh(acc[mt][ntl][2]);
                float v3 = ftanh(acc[mt][ntl][3]);
                int co = ntl*8 + tg*2;
                *(__half2*)(o0 + co) = __floats2half2_rn(v0, v1);
                *(__half2*)(o1 + co) = __floats2half2_rn(v2, v3);
                csum[ntl][0] += v0 + v2; csum[ntl][1] += v1 + v3;
                csq[ntl][0]  += v0*v0 + v2*v2; csq[ntl][1] += v1*v1 + v3*v3;
            }
        }
        #pragma unroll
        for (int ntl = 0; ntl < 3; ntl++)
            #pragma unroll
            for (int c2 = 0; c2 < 2; c2++) {
                float s = csum[ntl][c2], q = csq[ntl][c2];
                #pragma unroll
                for (int o = 16; o >= 4; o >>= 1) {
                    s += __shfl_down_sync(0xffffffffu, s, o);
                    q += __shfl_down_sync(0xffffffffu, q, o);
                }
                if (g == 0) {
                    int col = wn*24 + ntl*8 + tg*2 + c2;
                    atomicAdd(&s_red[col], s);
                    atomicAdd(&s_red[48 + col], q);
                }
            }
    }
    __syncthreads();
    for (int i = tid; i < 96; i += 256) atomicAdd(&red[i], s_red[i]);
}

// ---------------- direct 3x3 conv (FFMA2) — cm_ct / cm_c2 (R12 version) ----------------
template<int CIN_G, int OCB, int PAD, bool DOTANH, bool SAFE, bool PREBN>
__global__ void __launch_bounds__(256, 2)
k_conv3(const float* __restrict__ in, const float* __restrict__ wgt,
        const float* __restrict__ sbp, float* __restrict__ out,
        int H_in, int W_in, int H_out, int W_out, int C_in, int C_out, int tilesX) {
    __shared__ float s_tile[34*34];
    __shared__ alignas(16) float s_w[CIN_G*9*OCB];
    __shared__ float s_sc[CIN_G], s_bi[CIN_G];

    int tid = threadIdx.x;
    int oc_base = blockIdx.x * OCB;
    int groups = C_in / CIN_G;
    int oc_per_group = C_out / groups;
    int ic_base = (oc_base / oc_per_group) * CIN_G;

    for (int i = tid; i < CIN_G*9*OCB; i += 256) {
        int o = i % OCB, rest = i / OCB;
        s_w[i] = wgt[(long)(oc_base + o)*(CIN_G*9) + rest];
    }
    if (PREBN && tid < CIN_G) { s_sc[tid] = sbp[ic_base + tid]; s_bi[tid] = sbp[48 + ic_base + tid]; }

    int tX = blockIdx.y % tilesX, tY = blockIdx.y / tilesX;
    int ox0 = tX*32, oy0 = tY*32;
    int tx = tid & 31, ty = tid >> 5;

    int off[5]; bool vld[5];
    #pragma unroll
    for (int s = 0; s < 5; s++) {
        int j = tid + s*256;
        int ly = j / 34, lx = j - ly*34;
        int gy = oy0 - PAD + ly, gx = ox0 - PAD + lx;
        bool v = (j < 1156);
        if (SAFE) v = v && ((unsigned)gy < (unsigned)H_in) && ((unsigned)gx < (unsigned)W_in);
        vld[s] = v;
        off[s] = gy*W_in + gx;
    }

    const float* inb = in + ((long)blockIdx.z * C_in + ic_base) * H_in * W_in;
    float r[5];
    #pragma unroll
    for (int s = 0; s < 5; s++) r[s] = vld[s] ? __ldg(inb + off[s]) : 0.f;

    unsigned long long acc2[4][OCB/2];
    #pragma unroll
    for (int p = 0; p < 4; p++)
        #pragma unroll
        for (int j = 0; j < OCB/2; j++) acc2[p][j] = 0ull;

    __syncthreads();

    #pragma unroll 1
    for (int ic = 0; ic < CIN_G; ic++) {
        float sc = 0.f, bi = 0.f;
        if (PREBN) { sc = s_sc[ic]; bi = s_bi[ic]; }
        #pragma unroll
        for (int s = 0; s < 5; s++) {
            int j = tid + s*256;
            if (j < 1156) {
                float v = r[s];
                if (PREBN) v = ftanh(fmaf(sc, v, bi));
                s_tile[j] = v;
            }
        }
        __syncthreads();
        if (ic + 1 < CIN_G) {
            const float* src = inb + (long)(ic+1)*H_in*W_in;
            #pragma unroll
            for (int s = 0; s < 5; s++) r[s] = vld[s] ? __ldg(src + off[s]) : 0.f;
        }
        const float* wic = &s_w[ic*9*OCB];
        #pragma unroll
        for (int ky = 0; ky < 3; ky++) {
            float v[4][3];
            #pragma unroll
            for (int p = 0; p < 4; p++) {
                int base = (ty + 8*p + ky)*34 + tx;
                v[p][0] = s_tile[base]; v[p][1] = s_tile[base+1]; v[p][2] = s_tile[base+2];
            }
            #pragma unroll
            for (int kx = 0; kx < 3; kx++) {
                unsigned long long v2[4];
                #pragma unroll
                for (int p = 0; p < 4; p++) v2[p] = pack2(v[p][kx], v[p][kx]);
                if (OCB % 4 == 0) {
                    const float4* w4 = (const float4*)&wic[(ky*3 + kx)*OCB];
                    #pragma unroll
                    for (int q = 0; q < OCB/4; q++) {
                        float4 t4 = w4[q];
                        unsigned long long wA = pack2(t4.x, t4.y), wB = pack2(t4.z, t4.w);
                        #pragma unroll
                        for (int p = 0; p < 4; p++) {
                            ffma2(acc2[p][q*2],   v2[p], wA);
                            ffma2(acc2[p][q*2+1], v2[p], wB);
                        }
                    }
                } else {
                    #pragma unroll
                    for (int j = 0; j < OCB/2; j++) {
                        unsigned long long ww =
                            *(const unsigned long long*)&wic[(ky*3 + kx)*OCB + 2*j];
                        #pragma unroll
                        for (int p = 0; p < 4; p++) ffma2(acc2[p][j], v2[p], ww);
                    }
                }
            }
        }
        __syncthreads();
    }

    #pragma unroll
    for (int p = 0; p < 4; p++) {
        int oy = oy0 + ty + 8*p, ox = ox0 + tx;
        bool ok = (oy < H_out) && (ox < W_out);
        float* op = out + (((long)blockIdx.z*C_out + oc_base)*H_out + oy)*W_out + ox;
        long cs = (long)H_out*W_out;
        #pragma unroll
        for (int j = 0; j < OCB/2; j++) {
            float2 f = unpack2(acc2[p][j]);
            float v0 = DOTANH ? ftanh(f.x) : f.x;
            float v1 = DOTANH ? ftanh(f.y) : f.y;
            if (ok) { op[(2*j)*cs] = v0; op[(2*j+1)*cs] = v1; }
        }
    }
}

// CHANGE (h2 NHWC fp16)
__global__ void k_change(const __half* __restrict__ h2, const float* __restrict__ sb,
                         const float* __restrict__ w2, float* __restrict__ ch) {
    __shared__ float s_s[48], s_b[48], s_w[192];
    int t = threadIdx.x;
    if (t < 48) { s_s[t] = sb[t]; s_b[t] = sb[48+t]; }
    if (t < 192) s_w[t] = w2[t];
    __syncthreads();
    int idx = blockIdx.x*256 + t;
    int b = idx >> 14, pix = idx & 16383;
    int i = pix >> 7, j = pix & 127;
    const __half2* p00 = (const __half2*)(h2 + ((long)((b*256 + 2*i)*256) + 2*j)*48);
    const __half2* p01 = p00 + 24;
    const __half2* p10 = p00 + 256*24;
    const __half2* p11 = p10 + 24;
    float a = 0.f;
    #pragma unroll 4
    for (int c2 = 0; c2 < 24; c2++) {
        float2 v0 = __half22float2(p00[c2]);
        float2 v1 = __half22float2(p01[c2]);
        float2 v2 = __half22float2(p10[c2]);
        float2 v3 = __half22float2(p11[c2]);
        int c = c2*2;
        float s0 = s_s[c], b0 = s_b[c], s1 = s_s[c+1], b1 = s_b[c+1];
        a = fmaf(ftanh(fmaf(s0, v0.x, b0)), s_w[c*4+0],     a);
        a = fmaf(ftanh(fmaf(s1, v0.y, b1)), s_w[(c+1)*4+0], a);
        a = fmaf(ftanh(fmaf(s0, v1.x, b0)), s_w[c*4+1],     a);
        a = fmaf(ftanh(fmaf(s1, v1.y, b1)), s_w[(c+1)*4+1], a);
        a = fmaf(ftanh(fmaf(s0, v2.x, b0)), s_w[c*4+2],     a);
        a = fmaf(ftanh(fmaf(s1, v2.y, b1)), s_w[(c+1)*4+2], a);
        a = fmaf(ftanh(fmaf(s0, v3.x, b0)), s_w[c*4+3],     a);
        a = fmaf(ftanh(fmaf(s1, v3.y, b1)), s_w[(c+1)*4+3], a);
    }
    ch[idx] = fsig(a);
}

// cm conv1 (2x2 s2 g3) — 2 outputs/thread via float4 loads, fused reduction
__global__ void k_cm1red(const float* __restrict__ x, const float* __restrict__ w,
                         float* __restrict__ z, float* __restrict__ red) {
    __shared__ float ss[8], sq[8];
    int tid = threadIdx.x;
    int idx = blockIdx.x*256 + tid;            // Bn*48*8192 units of 2 outputs
    int b = idx / (48*8192); int r = idx - b*48*8192;
    int oc = r >> 13; int unit = r & 8191;
    int i = unit >> 6, u = unit & 63;
    int g = oc >> 4;
    const float* xp = x + ((long)b*6 + 2*g)*HW + (2*i)*256 + 4*u;
    const float* wp = w + oc*8;
    float4 a0 = *(const float4*)xp;
    float4 a1 = *(const float4*)(xp + 256);
    float4 b0 = *(const float4*)(xp + HW);
    float4 b1 = *(const float4*)(xp + HW + 256);
    float o0 = wp[0]*a0.x + wp[1]*a0.y + wp[2]*a1.x + wp[3]*a1.y
             + wp[4]*b0.x + wp[5]*b0.y + wp[6]*b1.x + wp[7]*b1.y;
    float o1 = wp[0]*a0.z + wp[1]*a0.w + wp[2]*a1.z + wp[3]*a1.w
             + wp[4]*b0.z + wp[5]*b0.w + wp[6]*b1.z + wp[7]*b1.w;
    *(float2*)(z + (long)idx*2) = make_float2(o0, o1);
    float s = o0 + o1, q = o0*o0 + o1*o1;
    #pragma unroll
    for (int d = 16; d > 0; d >>= 1) {
        s += __shfl_down_sync(0xffffffffu, s, d);
        q += __shfl_down_sync(0xffffffffu, q, d);
    }
    int warp = tid >> 5, lane = tid & 31;
    if (lane == 0) { ss[warp] = s; sq[warp] = q; }
    __syncthreads();
    if (tid == 0) {
        float S = 0.f, Q = 0.f;
        #pragma unroll
        for (int w8 = 0; w8 < 8; w8++) { S += ss[w8]; Q += sq[w8]; }
        atomicAdd(&red[oc], S); atomicAdd(&red[48 + oc], Q);
    }
}

__global__ void k_final(const float* __restrict__ xm, const float* __restrict__ ch,
                        const float* __restrict__ w1, const float* __restrict__ w2,
                        const float* __restrict__ sb, float* __restrict__ out) {
    __shared__ float s_w1[288], s_w2[288], s_s[48], s_b[48];
    int t = threadIdx.x;
    for (int i = t; i < 288; i += 256) { s_w1[i] = w1[i]; s_w2[i] = w2[i]; }
    if (t < 48)  { s_s[t] = sb[t]; s_b[t] = sb[48+t]; }
    __syncthreads();
    int idx = blockIdx.x*256 + t;
    int b = idx >> 14, pix = idx & 16383;
    const float* xp = xm + ((long)b*6)*HW2 + pix;
    float v[6];
    #pragma unroll
    for (int d = 0; d < 6; d++) v[d] = xp[d*HW2];
    float born[6] = {0,0,0,0,0,0};
    #pragma unroll 4
    for (int c = 0; c < 48; c++) {
        float y = s_w1[c*6]*v[0];
        #pragma unroll
        for (int d = 1; d < 6; d++) y = fmaf(s_w1[c*6+d], v[d], y);
        float h = ftanh(fmaf(s_s[c], y, s_b[c]));
        #pragma unroll
        for (int d = 0; d < 6; d++) born[d] = fmaf(s_w2[d*48+c], h, born[d]);
    }
    float cc = ch[idx];
    #pragma unroll
    for (int d = 0; d < 6; d++) {
        float o = v[d]*(1.f - cc) + cc*born[d];
        if (d < 3) o = fsig(o);
        out[((long)b*6 + d)*HW2 + pix] = o;
    }
}

// ---------------- launch (exact R12 structure) ----------------
extern "C" void kernel_launch(void* const* d_in, const int* in_sizes, int n_in,
                              void* d_out, int out_size) {
    const float* x     = (const float*)d_in[0];
    const float* ce_w1 = (const float*)d_in[1];
    const float* ce_g  = (const float*)d_in[2];
    const float* ce_b  = (const float*)d_in[3];
    const float* ce_w2 = (const float*)d_in[4];
    const float* md_ct = (const float*)d_in[5];
    const float* md_c1 = (const float*)d_in[6];
    const float* md_g  = (const float*)d_in[7];
    const float* md_b  = (const float*)d_in[8];
    const float* md_c2 = (const float*)d_in[9];
    const float* cm_w1 = (const float*)d_in[10];
    const float* cm_g  = (const float*)d_in[11];
    const float* cm_b  = (const float*)d_in[12];
    const float* cm_ct = (const float*)d_in[13];
    const float* cm_c2 = (const float*)d_in[14];
    const float* bo_w1 = (const float*)d_in[15];
    const float* bo_g  = (const float*)d_in[16];
    const float* bo_b  = (const float*)d_in[17];
    const float* bo_w2 = (const float*)d_in[18];

    float *E, *ch, *z, *hcm, *xm, *w5, *red, *sb;
    __half *h1, *h2;
    uint32_t *bfrag;
    cudaGetSymbolAddress((void**)&E,     g_E);
    cudaGetSymbolAddress((void**)&h1,    g_h1);
    cudaGetSymbolAddress((void**)&h2,    g_h2);
    cudaGetSymbolAddress((void**)&ch,    g_ch);
    cudaGetSymbolAddress((void**)&z,     g_z);
    cudaGetSymbolAddress((void**)&hcm,   g_hcm);
    cudaGetSymbolAddress((void**)&xm,    g_xm);
    cudaGetSymbolAddress((void**)&w5,    g_w5);
    cudaGetSymbolAddress((void**)&red,   g_red);
    cudaGetSymbolAddress((void**)&sb,    g_sb);
    cudaGetSymbolAddress((void**)&bfrag, g_bfrag);

    cudaFuncSetAttribute(k_hmma_mdc1, cudaFuncAttributeMaxDynamicSharedMemorySize, SMEM_TOT);

    const float invN_full = 1.f/(float)(Bn*HW);
    const float invN_half = 1.f/(float)(Bn*HW2);

    k_zero<<<1, 512>>>(red);

    // ---- fork: cell-merge chain on s2 ----
    cudaEventRecord(g_hx.e1, 0);
    cudaStreamWaitEvent(g_hx.s2, g_hx.e1, 0);

    k_cm1red<<<Bn*48*8192/256, 256, 0, g_hx.s2>>>(x, cm_w1, z, red + 138);
    k_bnsb<<<1, 64, 0, g_hx.s2>>>(red + 138, cm_g, cm_b, sb + 192, invN_half);
    k_conv3<16, 16, 2, true, true, true>
        <<<dim3(3, 25, Bn), 256, 0, g_hx.s2>>>(z, cm_ct, sb + 192, hcm,
                                               128, 128, 130, 130, 48, 48, 5);
    k_conv3<16, 2, 0, true, false, false>
        <<<dim3(3, 16, Bn), 256, 0, g_hx.s2>>>(hcm, cm_c2, nullptr, xm,
                                               130, 130, 128, 128, 48, 6, 4);
    k_mom6<<<64, 256, 0, g_hx.s2>>>(xm, red + 234, HW2);
    k_sb6 <<<1, 64, 0, g_hx.s2>>>(red + 234, bo_w1, bo_g, bo_b, sb + 288, invN_half);
    cudaEventRecord(g_hx.e2, g_hx.s2);

    // ---- md chain on default stream ----
    k_mom6<<<64, 256>>>(x, red + 0, HW);
    k_sb6 <<<1, 64>>>(red + 0, ce_w1, ce_g, ce_b, sb + 0, invN_full);
    k_env <<<Bn*HW/256, 256>>>(x, ce_w1, ce_w2, sb + 0, E);
    k_w5<<<1, 64>>>(md_ct, w5);
    k_wb<<<41, 256>>>(md_c1, bfrag);
    k_mdct<<<dim3(3, 64, Bn), 256>>>(x, E, w5, md_ct, h1);
    k_mdct_edge<<<dim3(8, Bn), 256>>>(x, E, md_ct, h1);
    k_hmma_mdc1<<<1024, 256, SMEM_TOT>>>(h1, bfrag, h2, red + 42);
    k_bnsb<<<1, 64>>>(red + 42, md_g, md_b, sb + 96, invN_full);
    k_change<<<Bn*HW2/256, 256>>>(h2, sb + 96, md_c2, ch);

    // ---- join, then final blend ----
    cudaStreamWaitEvent(0, g_hx.e2, 0);
    k_final<<<Bn*HW2/256, 256>>>(xm, ch, bo_w1, bo_w2, sb + 288, (float*)d_out);
}

// round 15
// speedup vs baseline: 1.4646x; 1.0746x over previous
#include <cuda_runtime.h>
#include <cuda_bf16.h>
#include <cuda_fp16.h>
#include <math.h>
#include <stdint.h>

#define Bn 8
#define Dc 6
#define NC 48
#define Hn 256
#define Wn 256
#define HW (Hn*Wn)
#define H2n 128
#define HW2 (H2n*H2n)

// ---------------- scratch ----------------
__device__ __half g_h1 [Bn*258*258*NC];          // NHWC fp16
__device__ float g_E  [Bn*HW];
__device__ __half g_h2 [Bn*NC*HW];               // NHWC fp16
__device__ float g_ch [Bn*HW2];
__device__ float g_z  [Bn*NC*HW2];
__device__ float g_hcm[Bn*NC*130*130];
__device__ float g_xm [Bn*Dc*HW2];
__device__ float g_w5 [25*NC];
__device__ uint32_t g_bfrag[9*3*6*32*2];         // B fragments [tap][kc][nt][lane][2]
__device__ float g_red[276];
__device__ float g_sb [384];

__device__ const int c_dx[8] = {0,1,1,1,0,-1,-1,-1};
__device__ const int c_dy[8] = {1,1,0,-1,-1,-1,0,1};

// ---- streams/events created at program init ----
struct HXStreams {
    cudaStream_t s2;
    cudaEvent_t e1, e2;
    HXStreams() {
        cudaStreamCreateWithFlags(&s2, cudaStreamNonBlocking);
        cudaEventCreateWithFlags(&e1, cudaEventDisableTiming);
        cudaEventCreateWithFlags(&e2, cudaEventDisableTiming);
    }
};
static HXStreams g_hx;

__device__ __forceinline__ float ftanh(float x) {
    x = fminf(fmaxf(x, -15.f), 15.f);
    float e = __expf(2.f*x);
    return __fdividef(e - 1.f, e + 1.f);
}
// fast tanh (SASS TANH, single op) — use ONLY on error-damped paths
__device__ __forceinline__ float ftanh_a(float x) {
    float y;
    asm("tanh.approx.f32 %0, %1;" : "=f"(y) : "f"(x));
    return y;
}
__device__ __forceinline__ float fsig(float x) {
    return __fdividef(1.f, 1.f + __expf(-x));
}

// ---- packed f32x2 ----
__device__ __forceinline__ unsigned long long pack2(float a, float b) {
    unsigned long long r;
    asm("mov.b64 %0, {%1, %2};" : "=l"(r) : "f"(a), "f"(b));
    return r;
}
__device__ __forceinline__ void ffma2(unsigned long long &d, unsigned long long a,
                                      unsigned long long b) {
    asm("fma.rn.f32x2 %0, %1, %2, %0;" : "+l"(d) : "l"(a), "l"(b));
}
__device__ __forceinline__ float2 unpack2(unsigned long long v) {
    float2 f;
    asm("mov.b64 {%0, %1}, %2;" : "=f"(f.x), "=f"(f.y) : "l"(v));
    return f;
}

// ---- warp mma + ldmatrix ----
__device__ __forceinline__ void mma16816(float* d, const uint32_t* a, uint32_t b0, uint32_t b1) {
    asm volatile("mma.sync.aligned.m16n8k16.row.col.f32.f16.f16.f32 "
        "{%0,%1,%2,%3}, {%4,%5,%6,%7}, {%8,%9}, {%0,%1,%2,%3};"
        : "+f"(d[0]), "+f"(d[1]), "+f"(d[2]), "+f"(d[3])
        : "r"(a[0]), "r"(a[1]), "r"(a[2]), "r"(a[3]), "r"(b0), "r"(b1));
}
__device__ __forceinline__ void ldsm_x4(uint32_t* r, uint32_t addr) {
    asm volatile("ldmatrix.sync.aligned.m8n8.x4.shared.b16 {%0,%1,%2,%3}, [%4];"
        : "=r"(r[0]), "=r"(r[1]), "=r"(r[2]), "=r"(r[3]) : "r"(addr));
}
__device__ __forceinline__ uint32_t smem_u32(const void* p) {
    uint32_t a;
    asm("{ .reg .u64 t; cvta.to.shared.u64 t, %1; cvt.u32.u64 %0, t; }" : "=r"(a) : "l"(p));
    return a;
}

// smem layout of k_hmma_mdc1 (dynamic): A staging + reduction only (B frags via L1)
#define SM_IN  0
#define SM_RED 43680
#define SMEM_TOT (SM_RED + 384)

// ---------------- tiny kernels ----------------
__global__ void k_zero(float* red) { if (threadIdx.x < 276) red[threadIdx.x] = 0.f; }

__global__ void k_mom6(const float* __restrict__ x, float* __restrict__ out, int hw) {
    float S[6] = {0,0,0,0,0,0};
    float P[21];
    #pragma unroll
    for (int i = 0; i < 21; i++) P[i] = 0.f;
    int total = Bn*hw;
    for (int t = blockIdx.x*blockDim.x + threadIdx.x; t < total; t += gridDim.x*blockDim.x) {
        int b = t / hw, i = t - b*hw;
        const float* p = x + (long)b*6*hw + i;
        float v[6];
        #pragma unroll
        for (int d = 0; d < 6; d++) v[d] = p[(long)d*hw];
        int idx = 0;
        #pragma unroll
        for (int d = 0; d < 6; d++) {
            S[d] += v[d];
            #pragma unroll
            for (int e = d; e < 6; e++) { P[idx] += v[d]*v[e]; idx++; }
        }
    }
    #pragma unroll
    for (int o = 16; o > 0; o >>= 1) {
        #pragma unroll
        for (int d = 0; d < 6; d++)  S[d] += __shfl_down_sync(0xffffffffu, S[d], o);
        #pragma unroll
        for (int i = 0; i < 21; i++) P[i] += __shfl_down_sync(0xffffffffu, P[i], o);
    }
    if ((threadIdx.x & 31) == 0) {
        #pragma unroll
        for (int d = 0; d < 6; d++)  atomicAdd(&out[d], S[d]);
        #pragma unroll
        for (int i = 0; i < 21; i++) atomicAdd(&out[6+i], P[i]);
    }
}

__global__ void k_sb6(const float* __restrict__ mom, const float* __restrict__ w1,
                      const float* __restrict__ g, const float* __restrict__ bt,
                      float* __restrict__ sb, float invN) {
    int c = threadIdx.x;
    if (c >= NC) return;
    float m = 0.f;
    #pragma unroll
    for (int d = 0; d < 6; d++) m += w1[c*6+d]*mom[d];
    m *= invN;
    float q = 0.f; int idx = 0;
    #pragma unroll
    for (int d = 0; d < 6; d++)
        #pragma unroll
        for (int e = d; e < 6; e++) {
            float coef = (d == e) ? 1.f : 2.f;
            q += coef * w1[c*6+d]*w1[c*6+e]*mom[6+idx];
            idx++;
        }
    q *= invN;
    float var = q - m*m;
    float sc = g[c]*rsqrtf(var + 1e-5f);
    sb[c] = sc; sb[NC+c] = bt[c] - m*sc;
}

__global__ void k_bnsb(const float* __restrict__ sums, const float* __restrict__ g,
                       const float* __restrict__ bt, float* __restrict__ sb, float invN) {
    int c = threadIdx.x;
    if (c >= NC) return;
    float m = sums[c]*invN;
    float var = sums[NC+c]*invN - m*m;
    float sc = g[c]*rsqrtf(var + 1e-5f);
    sb[c] = sc; sb[NC+c] = bt[c] - m*sc;
}

__global__ void k_env(const float* __restrict__ x, const float* __restrict__ w1,
                      const float* __restrict__ w2, const float* __restrict__ sb,
                      float* __restrict__ E) {
    __shared__ float s_w1[288], s_w2[48], s_s[48], s_b[48];
    int t = threadIdx.x;
    for (int i = t; i < 288; i += 256) s_w1[i] = w1[i];
    if (t < 48) { s_w2[t] = w2[t]; s_s[t] = sb[t]; s_b[t] = sb[48+t]; }
    __syncthreads();
    int idx = blockIdx.x*256 + t;
    int b = idx >> 16, pix = idx & 65535;
    const float* xp = x + (long)b*6*HW + pix;
    float v[6];
    #pragma unroll
    for (int d = 0; d < 6; d++) v[d] = xp[(long)d*HW];
    float e = 0.f;
    #pragma unroll 4
    for (int c = 0; c < 48; c++) {
        float y = s_w1[c*6]*v[0];
        #pragma unroll
        for (int d = 1; d < 6; d++) y = fmaf(s_w1[c*6+d], v[d], y);
        e = fmaf(s_w2[c], ftanh(fmaf(s_s[c], y, s_b[c])), e);
    }
    E[idx] = e;
}

__global__ void k_w5(const float* __restrict__ md_ct, float* __restrict__ W5) {
    int oc = threadIdx.x;
    if (oc >= 48) return;
    float w5[25];
    #pragma unroll
    for (int i = 0; i < 25; i++) w5[i] = 0.f;
    for (int k = 0; k < 8; k++)
        for (int ky = 0; ky < 3; ky++)
            for (int kx = 0; kx < 3; kx++) {
                int u = ky - 2 + c_dy[k] + 3;
                int v = kx - 2 - c_dx[k] + 3;
                w5[u*5+v] += md_ct[oc*90 + (k+2)*9 + ky*3 + kx];
            }
    for (int i = 0; i < 25; i++) W5[i*48 + oc] = w5[i];
}

// md_c1 weights -> fp16 B fragments in mma register order
__global__ void k_wb(const float* __restrict__ md_c1, uint32_t* __restrict__ bfrag) {
    int i = blockIdx.x*256 + threadIdx.x;
    if (i >= 9*3*6*32*2) return;
    int r    = i & 1;
    int lane = (i >> 1) & 31;
    int nt   = (i >> 6) % 6;
    int kc   = (i / (64*6)) % 3;
    int tap  = i / (64*6*3);
    int n  = nt*8 + (lane >> 2);
    int k0 = (lane & 3)*2 + r*8;
    float w0 = md_c1[((n*48) + kc*16 + k0    )*9 + tap];
    float w1 = md_c1[((n*48) + kc*16 + k0 + 1)*9 + tap];
    __half2 pk;
    pk.x = __float2half_rn(w0);
    pk.y = __float2half_rn(w1);
    bfrag[i] = *(uint32_t*)&pk;
}

__device__ __forceinline__ void store_h2(__half* h1, long base, float v0, float v1) {
    __half2 p;
    p.x = __float2half_rn(v0);
    p.y = __float2half_rn(v1);
    *(uint32_t*)(h1 + base) = *(uint32_t*)&p;
}

// md_ct interior (FFMA2), outputs NHWC fp16
__global__ void __launch_bounds__(256, 2)
k_mdct(const float* __restrict__ x, const float* __restrict__ E,
       const float* __restrict__ W5, const float* __restrict__ md_ct,
       __half* __restrict__ h1) {
    __shared__ float sE[36*36];
    __shared__ float sx[2][34*34];
    __shared__ alignas(16) float s_w5[25*16];
    __shared__ alignas(16) float s_w3[2*9*16];
    int tid = threadIdx.x;
    int oc_base = blockIdx.x * 16;
    int b = blockIdx.z;
    int tX = blockIdx.y & 7, tY = blockIdx.y >> 3;
    int p0 = 2 + tY*32, q0 = 2 + tX*32;

    for (int i = tid; i < 25*16; i += 256) {
        int tap = i >> 4, o = i & 15;
        s_w5[i] = W5[tap*48 + oc_base + o];
    }
    for (int i = tid; i < 288; i += 256) {
        int o = i & 15, rest = i >> 4;
        s_w3[i] = md_ct[(oc_base + o)*90 + rest];
    }
    for (int i = tid; i < 1296; i += 256) {
        int lr = i / 36, lc = i - lr*36;
        int gy = (p0 - 3 + lr) & 255, gx = (q0 - 3 + lc) & 255;
        sE[i] = E[b*HW + (gy << 8) + gx];
    }
    #pragma unroll
    for (int ch = 0; ch < 2; ch++)
        for (int i = tid; i < 1156; i += 256) {
            int lr = i / 34, lc = i - lr*34;
            int gy = p0 - 2 + lr, gx = q0 - 2 + lc;
            float v = 0.f;
            if (gy < 256 && gx < 256) v = x[((long)b*6 + ch)*HW + (gy << 8) + gx];
            sx[ch][i] = v;
        }
    __syncthreads();

    int tx = tid & 31, ty = tid >> 5;
    unsigned long long acc2[4][8];
    #pragma unroll
    for (int p = 0; p < 4; p++)
        #pragma unroll
        for (int j = 0; j < 8; j++) acc2[p][j] = 0ull;

    #pragma unroll
    for (int u = 0; u < 5; u++) {
        float v[4][5];
        #pragma unroll
        for (int p = 0; p < 4; p++) {
            int base = (ty + 8*p + u)*36 + tx;
            #pragma unroll
            for (int j = 0; j < 5; j++) v[p][j] = sE[base + j];
        }
        #pragma unroll
        for (int vv = 0; vv < 5; vv++) {
            unsigned long long v2[4];
            #pragma unroll
            for (int p = 0; p < 4; p++) v2[p] = pack2(v[p][vv], v[p][vv]);
            const float4* w4 = (const float4*)&s_w5[(u*5 + vv)*16];
            #pragma unroll
            for (int q = 0; q < 4; q++) {
                float4 t4 = w4[q];
                unsigned long long wA = pack2(t4.x, t4.y), wB = pack2(t4.z, t4.w);
                #pragma unroll
                for (int p = 0; p < 4; p++) {
                    ffma2(acc2[p][q*2],   v2[p], wA);
                    ffma2(acc2[p][q*2+1], v2[p], wB);
                }
            }
        }
    }
    #pragma unroll
    for (int ch = 0; ch < 2; ch++)
        #pragma unroll
        for (int ky = 0; ky < 3; ky++) {
            float v[4][3];
            #pragma unroll
            for (int p = 0; p < 4; p++) {
                int base = (ty + 8*p + ky)*34 + tx;
                v[p][0] = sx[ch][base]; v[p][1] = sx[ch][base+1]; v[p][2] = sx[ch][base+2];
            }
            #pragma unroll
            for (int kx = 0; kx < 3; kx++) {
                unsigned long long v2[4];
                #pragma unroll
                for (int p = 0; p < 4; p++) v2[p] = pack2(v[p][kx], v[p][kx]);
                const float4* w4 = (const float4*)&s_w3[(ch*9 + ky*3 + kx)*16];
                #pragma unroll
                for (int q = 0; q < 4; q++) {
                    float4 t4 = w4[q];
                    unsigned long long wA = pack2(t4.x, t4.y), wB = pack2(t4.z, t4.w);
                    #pragma unroll
                    for (int p = 0; p < 4; p++) {
                        ffma2(acc2[p][q*2],   v2[p], wA);
                        ffma2(acc2[p][q*2+1], v2[p], wB);
                    }
                }
            }
        }

    #pragma unroll
    for (int p = 0; p < 4; p++) {
        int pp = p0 + ty + 8*p, qq = q0 + tx;
        if (pp <= 255 && qq <= 255) {
            long base = ((long)(b*258 + pp)*258 + qq)*48 + oc_base;
            #pragma unroll
            for (int j = 0; j < 8; j++) {
                float2 f = unpack2(acc2[p][j]);
                store_h2(h1, base + 2*j, ftanh(f.x), ftanh(f.y));
            }
        }
    }
}

// md_ct boundary
__global__ void k_mdct_edge(const float* __restrict__ x, const float* __restrict__ E,
                            const float* __restrict__ md_ct, __half* __restrict__ h1) {
    __shared__ float s_w[4320];
    int tid = threadIdx.x;
    for (int i = tid; i < 4320; i += 256) {
        int oc = i % 48, rest = i / 48;
        s_w[rest*48 + oc] = md_ct[oc*90 + rest];
    }
    __syncthreads();
    int idx = blockIdx.x*256 + tid;
    int b = blockIdx.y;
    int p, q;
    if (idx < 1032) { int r = idx/258; p = (r < 2) ? r : 254 + r; q = idx - r*258; }
    else { int j = idx - 1032; int c = j/254; q = (c < 2) ? c : 254 + c; p = 2 + (j - c*254); }
    float acc[48];
    #pragma unroll
    for (int o = 0; o < 48; o++) acc[o] = 0.f;
    for (int ch = 0; ch < 10; ch++)
        for (int ky = 0; ky < 3; ky++)
            for (int kx = 0; kx < 3; kx++) {
                int y = p - 2 + ky, xx = q - 2 + kx;
                if ((unsigned)y < 256u && (unsigned)xx < 256u) {
                    float v;
                    if (ch < 2) v = x[((long)b*6 + ch)*HW + (y << 8) + xx];
                    else {
                        int k = ch - 2;
                        v = E[b*HW + (((y + c_dy[k]) & 255) << 8) + ((xx - c_dx[k]) & 255)];
                    }
                    const float* wr = &s_w[(ch*9 + ky*3 + kx)*48];
                    #pragma unroll
                    for (int o = 0; o < 48; o++) acc[o] = fmaf(v, wr[o], acc[o]);
                }
            }
    long base = ((long)(b*258 + p)*258 + q)*48;
    #pragma unroll
    for (int o = 0; o < 48; o += 2)
        store_h2(h1, base + o, ftanh(acc[o]), ftanh(acc[o+1]));
}

// ---------------- md_c1 via warp fp16 mma (ldmatrix A, B frags from L1) ----------------
__global__ void __launch_bounds__(256, 3)
k_hmma_mdc1(const __half* __restrict__ h1, const uint32_t* __restrict__ bfrag,
            __half* __restrict__ h2, float* __restrict__ red) {
    extern __shared__ char smem[];
    uint32_t* sA  = (uint32_t*)(smem + SM_IN);
    float* s_red  = (float*)(smem + SM_RED);
    uint32_t sA_addr = smem_u32(smem) + SM_IN;

    int tid = threadIdx.x, wid = tid >> 5, lane = tid & 31;
    int wm = wid >> 1, wn = wid & 1;
    int g = lane >> 2, tg = lane & 3;
    int m0 = wm * 32;
    uint32_t roff = (uint32_t)(((lane & 15)*28 + (lane >> 4)*4) * 4);
    const uint2* bf = (const uint2*)bfrag + lane;

    if (tid < 96) s_red[tid] = 0.f;

    for (int t = 0; t < 4; t++) {
        int gt = blockIdx.x*4 + t;
        int hf = gt & 1, p = (gt >> 1) & 255, b = gt >> 9;
        int q0 = hf << 7;

        __syncthreads();
        const uint4* srcA = (const uint4*)(h1 + ((long)(b*258 + p)*258 + q0)*48);
        uint4* dstA = (uint4*)sA;
        for (int i = tid; i < 3*130*6; i += 256) {
            int px = i / 6, w4 = i - px*6;
            int ky = px / 130, lp = px - ky*130;
            dstA[px*7 + w4] = srcA[(long)ky*(258*6) + lp*6 + w4];
        }
        __syncthreads();

        float acc[2][3][4];
        #pragma unroll
        for (int mt = 0; mt < 2; mt++)
            #pragma unroll
            for (int nt = 0; nt < 3; nt++)
                #pragma unroll
                for (int r = 0; r < 4; r++) acc[mt][nt][r] = 0.f;

        #pragma unroll 1
        for (int tap = 0; tap < 9; tap++) {
            int ky = tap/3, kx = tap - ky*3;
            int rowbase = ky*130 + m0 + kx;
            #pragma unroll
            for (int kc = 0; kc < 3; kc++) {
                const uint2* bp = bf + ((tap*3 + kc)*6 + wn*3)*32;
                uint2 b0 = __ldg(bp);
                uint2 b1 = __ldg(bp + 32);
                uint2 b2 = __ldg(bp + 64);
                uint32_t ah[2][4];
                #pragma unroll
                for (int mt = 0; mt < 2; mt++) {
                    uint32_t addr = sA_addr + (uint32_t)((rowbase + mt*16)*112 + kc*32) + roff;
                    ldsm_x4(ah[mt], addr);
                }
                #pragma unroll
                for (int mt = 0; mt < 2; mt++) {
                    mma16816(acc[mt][0], ah[mt], b0.x, b0.y);
                    mma16816(acc[mt][1], ah[mt], b1.x, b1.y);
                    mma16816(acc[mt][2], ah[mt], b2.x, b2.y);
                }
            }
        }

        float csum[3][2], csq[3][2];
        #pragma unroll
        for (int ntl = 0; ntl < 3; ntl++) { csum[ntl][0]=0.f; csum[ntl][1]=0.f; csq[ntl][0]=0.f; csq[ntl][1]=0.f; }
        #pragma unroll
        for (int mt = 0; mt < 2; mt++) {
            int pr0 = q0 + m0 + mt*16 + g;
            __half* o0 = h2 + ((long)((b*256 + p)*256) + pr0)*48 + wn*24;
            __half* o1 = o0 + 8*48;
            #pragma unroll
            for (int ntl = 0; ntl < 3; ntl++) {
                float v0 = ftanh(acc[mt][ntl][0]);
                float v1 = ftanh(acc[mt][ntl][1]);
                float v2 = ftanh(acc[mt][ntl][2]);
                float v3 = ftanh(acc[mt][ntl][3]);
                int co = ntl*8 + tg*2;
                *(__half2*)(o0 + co) = __floats2half2_rn(v0, v1);
                *(__half2*)(o1 + co) = __floats2half2_rn(v2, v3);
                csum[ntl][0] += v0 + v2; csum[ntl][1] += v1 + v3;
                csq[ntl][0]  += v0*v0 + v2*v2; csq[ntl][1] += v1*v1 + v3*v3;
            }
        }
        #pragma unroll
        for (int ntl = 0; ntl < 3; ntl++)
            #pragma unroll
            for (int c2 = 0; c2 < 2; c2++) {
                float s = csum[ntl][c2], q = csq[ntl][c2];
                #pragma unroll
                for (int o = 16; o >= 4; o >>= 1) {
                    s += __shfl_down_sync(0xffffffffu, s, o);
                    q += __shfl_down_sync(0xffffffffu, q, o);
                }
                if (g == 0) {
                    int col = wn*24 + ntl*8 + tg*2 + c2;
                    atomicAdd(&s_red[col], s);
                    atomicAdd(&s_red[48 + col], q);
                }
            }
    }
    __syncthreads();
    for (int i = tid; i < 96; i += 256) atomicAdd(&red[i], s_red[i]);
}

// ---------------- direct 3x3 conv (FFMA2) — cm_ct / cm_c2 ----------------
template<int CIN_G, int OCB, int PAD, bool DOTANH, bool SAFE, bool PREBN>
__global__ void __launch_bounds__(256, 2)
k_conv3(const float* __restrict__ in, const float* __restrict__ wgt,
        const float* __restrict__ sbp, float* __restrict__ out,
        int H_in, int W_in, int H_out, int W_out, int C_in, int C_out, int tilesX) {
    __shared__ float s_tile[34*34];
    __shared__ alignas(16) float s_w[CIN_G*9*OCB];
    __shared__ float s_sc[CIN_G], s_bi[CIN_G];

    int tid = threadIdx.x;
    int oc_base = blockIdx.x * OCB;
    int groups = C_in / CIN_G;
    int oc_per_group = C_out / groups;
    int ic_base = (oc_base / oc_per_group) * CIN_G;

    for (int i = tid; i < CIN_G*9*OCB; i += 256) {
        int o = i % OCB, rest = i / OCB;
        s_w[i] = wgt[(long)(oc_base + o)*(CIN_G*9) + rest];
    }
    if (PREBN && tid < CIN_G) { s_sc[tid] = sbp[ic_base + tid]; s_bi[tid] = sbp[48 + ic_base + tid]; }

    int tX = blockIdx.y % tilesX, tY = blockIdx.y / tilesX;
    int ox0 = tX*32, oy0 = tY*32;
    int tx = tid & 31, ty = tid >> 5;

    int off[5]; bool vld[5];
    #pragma unroll
    for (int s = 0; s < 5; s++) {
        int j = tid + s*256;
        int ly = j / 34, lx = j - ly*34;
        int gy = oy0 - PAD + ly, gx = ox0 - PAD + lx;
        bool v = (j < 1156);
        if (SAFE) v = v && ((unsigned)gy < (unsigned)H_in) && ((unsigned)gx < (unsigned)W_in);
        vld[s] = v;
        off[s] = gy*W_in + gx;
    }

    const float* inb = in + ((long)blockIdx.z * C_in + ic_base) * H_in * W_in;
    float r[5];
    #pragma unroll
    for (int s = 0; s < 5; s++) r[s] = vld[s] ? __ldg(inb + off[s]) : 0.f;

    unsigned long long acc2[4][OCB/2];
    #pragma unroll
    for (int p = 0; p < 4; p++)
        #pragma unroll
        for (int j = 0; j < OCB/2; j++) acc2[p][j] = 0ull;

    __syncthreads();

    #pragma unroll 1
    for (int ic = 0; ic < CIN_G; ic++) {
        float sc = 0.f, bi = 0.f;
        if (PREBN) { sc = s_sc[ic]; bi = s_bi[ic]; }
        #pragma unroll
        for (int s = 0; s < 5; s++) {
            int j = tid + s*256;
            if (j < 1156) {
                float v = r[s];
                if (PREBN) v = ftanh(fmaf(sc, v, bi));
                s_tile[j] = v;
            }
        }
        __syncthreads();
        if (ic + 1 < CIN_G) {
            const float* src = inb + (long)(ic+1)*H_in*W_in;
            #pragma unroll
            for (int s = 0; s < 5; s++) r[s] = vld[s] ? __ldg(src + off[s]) : 0.f;
        }
        const float* wic = &s_w[ic*9*OCB];
        #pragma unroll
        for (int ky = 0; ky < 3; ky++) {
            float v[4][3];
            #pragma unroll
            for (int p = 0; p < 4; p++) {
                int base = (ty + 8*p + ky)*34 + tx;
                v[p][0] = s_tile[base]; v[p][1] = s_tile[base+1]; v[p][2] = s_tile[base+2];
            }
            #pragma unroll
            for (int kx = 0; kx < 3; kx++) {
                unsigned long long v2[4];
                #pragma unroll
                for (int p = 0; p < 4; p++) v2[p] = pack2(v[p][kx], v[p][kx]);
                if (OCB % 4 == 0) {
                    const float4* w4 = (const float4*)&wic[(ky*3 + kx)*OCB];
                    #pragma unroll
                    for (int q = 0; q < OCB/4; q++) {
                        float4 t4 = w4[q];
                        unsigned long long wA = pack2(t4.x, t4.y), wB = pack2(t4.z, t4.w);
                        #pragma unroll
                        for (int p = 0; p < 4; p++) {
                            ffma2(acc2[p][q*2],   v2[p], wA);
                            ffma2(acc2[p][q*2+1], v2[p], wB);
                        }
                    }
                } else {
                    #pragma unroll
                    for (int j = 0; j < OCB/2; j++) {
                        unsigned long long ww =
                            *(const unsigned long long*)&wic[(ky*3 + kx)*OCB + 2*j];
                        #pragma unroll
                        for (int p = 0; p < 4; p++) ffma2(acc2[p][j], v2[p], ww);
                    }
                }
            }
        }
        __syncthreads();
    }

    #pragma unroll
    for (int p = 0; p < 4; p++) {
        int oy = oy0 + ty + 8*p, ox = ox0 + tx;
        bool ok = (oy < H_out) && (ox < W_out);
        float* op = out + (((long)blockIdx.z*C_out + oc_base)*H_out + oy)*W_out + ox;
        long cs = (long)H_out*W_out;
        #pragma unroll
        for (int j = 0; j < OCB/2; j++) {
            float2 f = unpack2(acc2[p][j]);
            float v0 = DOTANH ? ftanh(f.x) : f.x;
            float v1 = DOTANH ? ftanh(f.y) : f.y;
            if (ok) { op[(2*j)*cs] = v0; op[(2*j+1)*cs] = v1; }
        }
    }
}

// CHANGE (h2 NHWC fp16) — float4 loads (8 ch/load), fast tanh on damped path
__global__ void k_change(const __half* __restrict__ h2, const float* __restrict__ sb,
                         const float* __restrict__ w2, float* __restrict__ ch) {
    __shared__ float s_s[48], s_b[48], s_w[192];
    int t = threadIdx.x;
    if (t < 48) { s_s[t] = sb[t]; s_b[t] = sb[48+t]; }
    if (t < 192) s_w[t] = w2[t];
    __syncthreads();
    int idx = blockIdx.x*256 + t;
    int b = idx >> 14, pix = idx & 16383;
    int i = pix >> 7, j = pix & 127;
    const float4* q00 = (const float4*)(h2 + ((long)((b*256 + 2*i)*256) + 2*j)*48);
    const float4* q01 = q00 + 6;          // +48 halves
    const float4* q10 = q00 + 256*6;      // +256*48 halves
    const float4* q11 = q10 + 6;
    float a = 0.f;
    #pragma unroll
    for (int c8 = 0; c8 < 6; c8++) {
        float4 r0 = q00[c8], r1 = q01[c8], r2 = q10[c8], r3 = q11[c8];
        const __half2* h0 = (const __half2*)&r0;
        const __half2* h1v = (const __half2*)&r1;
        const __half2* h2v = (const __half2*)&r2;
        const __half2* h3 = (const __half2*)&r3;
        #pragma unroll
        for (int k2 = 0; k2 < 4; k2++) {
            int c = c8*8 + k2*2;
            float2 v0 = __half22float2(h0[k2]);
            float2 v1 = __half22float2(h1v[k2]);
            float2 v2 = __half22float2(h2v[k2]);
            float2 v3 = __half22float2(h3[k2]);
            float s0 = s_s[c], b0 = s_b[c], s1 = s_s[c+1], b1 = s_b[c+1];
            a = fmaf(ftanh_a(fmaf(s0, v0.x, b0)), s_w[c*4+0],     a);
            a = fmaf(ftanh_a(fmaf(s1, v0.y, b1)), s_w[(c+1)*4+0], a);
            a = fmaf(ftanh_a(fmaf(s0, v1.x, b0)), s_w[c*4+1],     a);
            a = fmaf(ftanh_a(fmaf(s1, v1.y, b1)), s_w[(c+1)*4+1], a);
            a = fmaf(ftanh_a(fmaf(s0, v2.x, b0)), s_w[c*4+2],     a);
            a = fmaf(ftanh_a(fmaf(s1, v2.y, b1)), s_w[(c+1)*4+2], a);
            a = fmaf(ftanh_a(fmaf(s0, v3.x, b0)), s_w[c*4+3],     a);
            a = fmaf(ftanh_a(fmaf(s1, v3.y, b1)), s_w[(c+1)*4+3], a);
        }
    }
    ch[idx] = fsig(a);
}

// cm conv1 (2x2 s2 g3) — 2 outputs/thread via float4 loads, fused reduction
__global__ void k_cm1red(const float* __restrict__ x, const float* __restrict__ w,
                         float* __restrict__ z, float* __restrict__ red) {
    __shared__ float ss[8], sq[8];
    int tid = threadIdx.x;
    int idx = blockIdx.x*256 + tid;
    int b = idx / (48*8192); int r = idx - b*48*8192;
    int oc = r >> 13; int unit = r & 8191;
    int i = unit >> 6, u = unit & 63;
    int g = oc >> 4;
    const float* xp = x + ((long)b*6 + 2*g)*HW + (2*i)*256 + 4*u;
    const float* wp = w + oc*8;
    float4 a0 = *(const float4*)xp;
    float4 a1 = *(const float4*)(xp + 256);
    float4 b0 = *(const float4*)(xp + HW);
    float4 b1 = *(const float4*)(xp + HW + 256);
    float o0 = wp[0]*a0.x + wp[1]*a0.y + wp[2]*a1.x + wp[3]*a1.y
             + wp[4]*b0.x + wp[5]*b0.y + wp[6]*b1.x + wp[7]*b1.y;
    float o1 = wp[0]*a0.z + wp[1]*a0.w + wp[2]*a1.z + wp[3]*a1.w
             + wp[4]*b0.z + wp[5]*b0.w + wp[6]*b1.z + wp[7]*b1.w;
    *(float2*)(z + (long)idx*2) = make_float2(o0, o1);
    float s = o0 + o1, q = o0*o0 + o1*o1;
    #pragma unroll
    for (int d = 16; d > 0; d >>= 1) {
        s += __shfl_down_sync(0xffffffffu, s, d);
        q += __shfl_down_sync(0xffffffffu, q, d);
    }
    int warp = tid >> 5, lane = tid & 31;
    if (lane == 0) { ss[warp] = s; sq[warp] = q; }
    __syncthreads();
    if (tid == 0) {
        float S = 0.f, Q = 0.f;
        #pragma unroll
        for (int w8 = 0; w8 < 8; w8++) { S += ss[w8]; Q += sq[w8]; }
        atomicAdd(&red[oc], S); atomicAdd(&red[48 + oc], Q);
    }
}

__global__ void k_final(const float* __restrict__ xm, const float* __restrict__ ch,
                        const float* __restrict__ w1, const float* __restrict__ w2,
                        const float* __restrict__ sb, float* __restrict__ out) {
    __shared__ float s_w1[288], s_w2[288], s_s[48], s_b[48];
    int t = threadIdx.x;
    for (int i = t; i < 288; i += 256) { s_w1[i] = w1[i]; s_w2[i] = w2[i]; }
    if (t < 48)  { s_s[t] = sb[t]; s_b[t] = sb[48+t]; }
    __syncthreads();
    int idx = blockIdx.x*256 + t;
    int b = idx >> 14, pix = idx & 16383;
    const float* xp = xm + ((long)b*6)*HW2 + pix;
    float v[6];
    #pragma unroll
    for (int d = 0; d < 6; d++) v[d] = xp[d*HW2];
    float born[6] = {0,0,0,0,0,0};
    #pragma unroll 4
    for (int c = 0; c < 48; c++) {
        float y = s_w1[c*6]*v[0];
        #pragma unroll
        for (int d = 1; d < 6; d++) y = fmaf(s_w1[c*6+d], v[d], y);
        float h = ftanh_a(fmaf(s_s[c], y, s_b[c]));   // damped path (born weights ~0.1, xC<=1)
        #pragma unroll
        for (int d = 0; d < 6; d++) born[d] = fmaf(s_w2[d*48+c], h, born[d]);
    }
    float cc = ch[idx];
    #pragma unroll
    for (int d = 0; d < 6; d++) {
        float o = v[d]*(1.f - cc) + cc*born[d];
        if (d < 3) o = fsig(o);
        out[((long)b*6 + d)*HW2 + pix] = o;
    }
}

// ---------------- launch (R12 structure) ----------------
extern "C" void kernel_launch(void* const* d_in, const int* in_sizes, int n_in,
                              void* d_out, int out_size) {
    const float* x     = (const float*)d_in[0];
    const float* ce_w1 = (const float*)d_in[1];
    const float* ce_g  = (const float*)d_in[2];
    const float* ce_b  = (const float*)d_in[3];
    const float* ce_w2 = (const float*)d_in[4];
    const float* md_ct = (const float*)d_in[5];
    const float* md_c1 = (const float*)d_in[6];
    const float* md_g  = (const float*)d_in[7];
    const float* md_b  = (const float*)d_in[8];
    const float* md_c2 = (const float*)d_in[9];
    const float* cm_w1 = (const float*)d_in[10];
    const float* cm_g  = (const float*)d_in[11];
    const float* cm_b  = (const float*)d_in[12];
    const float* cm_ct = (const float*)d_in[13];
    const float* cm_c2 = (const float*)d_in[14];
    const float* bo_w1 = (const float*)d_in[15];
    const float* bo_g  = (const float*)d_in[16];
    const float* bo_b  = (const float*)d_in[17];
    const float* bo_w2 = (const float*)d_in[18];

    float *E, *ch, *z, *hcm, *xm, *w5, *red, *sb;
    __half *h1, *h2;
    uint32_t *bfrag;
    cudaGetSymbolAddress((void**)&E,     g_E);
    cudaGetSymbolAddress((void**)&h1,    g_h1);
    cudaGetSymbolAddress((void**)&h2,    g_h2);
    cudaGetSymbolAddress((void**)&ch,    g_ch);
    cudaGetSymbolAddress((void**)&z,     g_z);
    cudaGetSymbolAddress((void**)&hcm,   g_hcm);
    cudaGetSymbolAddress((void**)&xm,    g_xm);
    cudaGetSymbolAddress((void**)&w5,    g_w5);
    cudaGetSymbolAddress((void**)&red,   g_red);
    cudaGetSymbolAddress((void**)&sb,    g_sb);
    cudaGetSymbolAddress((void**)&bfrag, g_bfrag);

    cudaFuncSetAttribute(k_hmma_mdc1, cudaFuncAttributeMaxDynamicSharedMemorySize, SMEM_TOT);

    const float invN_full = 1.f/(float)(Bn*HW);
    const float invN_half = 1.f/(float)(Bn*HW2);

    k_zero<<<1, 512>>>(red);

    // ---- fork: cell-merge chain on s2 ----
    cudaEventRecord(g_hx.e1, 0);
    cudaStreamWaitEvent(g_hx.s2, g_hx.e1, 0);

    k_cm1red<<<Bn*48*8192/256, 256, 0, g_hx.s2>>>(x, cm_w1, z, red + 138);
    k_bnsb<<<1, 64, 0, g_hx.s2>>>(red + 138, cm_g, cm_b, sb + 192, invN_half);
    k_conv3<16, 16, 2, true, true, true>
        <<<dim3(3, 25, Bn), 256, 0, g_hx.s2>>>(z, cm_ct, sb + 192, hcm,
                                               128, 128, 130, 130, 48, 48, 5);
    k_conv3<16, 2, 0, true, false, false>
        <<<dim3(3, 16, Bn), 256, 0, g_hx.s2>>>(hcm, cm_c2, nullptr, xm,
                                               130, 130, 128, 128, 48, 6, 4);
    k_mom6<<<64, 256, 0, g_hx.s2>>>(xm, red + 234, HW2);
    k_sb6 <<<1, 64, 0, g_hx.s2>>>(red + 234, bo_w1, bo_g, bo_b, sb + 288, invN_half);
    cudaEventRecord(g_hx.e2, g_hx.s2);

    // ---- md chain on default stream ----
    k_mom6<<<64, 256>>>(x, red + 0, HW);
    k_sb6 <<<1, 64>>>(red + 0, ce_w1, ce_g, ce_b, sb + 0, invN_full);
    k_env <<<Bn*HW/256, 256>>>(x, ce_w1, ce_w2, sb + 0, E);
    k_w5<<<1, 64>>>(md_ct, w5);
    k_wb<<<41, 256>>>(md_c1, bfrag);
    k_mdct<<<dim3(3, 64, Bn), 256>>>(x, E, w5, md_ct, h1);
    k_mdct_edge<<<dim3(8, Bn), 256>>>(x, E, md_ct, h1);
    k_hmma_mdc1<<<1024, 256, SMEM_TOT>>>(h1, bfrag, h2, red + 42);
    k_bnsb<<<1, 64>>>(red + 42, md_g, md_b, sb + 96, invN_full);
    k_change<<<Bn*HW2/256, 256>>>(h2, sb + 96, md_c2, ch);

    // ---- join, then final blend ----
    cudaStreamWaitEvent(0, g_hx.e2, 0);
    k_final<<<Bn*HW2/256, 256>>>(xm, ch, bo_w1, bo_w2, sb + 288, (float*)d_out);
}

// round 16
// speedup vs baseline: 1.4958x; 1.0213x over previous
#include <cuda_runtime.h>
#include <cuda_bf16.h>
#include <cuda_fp16.h>
#include <math.h>
#include <stdint.h>

#define Bn 8
#define Dc 6
#define NC 48
#define Hn 256
#define Wn 256
#define HW (Hn*Wn)
#define H2n 128
#define HW2 (H2n*H2n)

// ---------------- scratch ----------------
__device__ __half g_h1 [Bn*258*258*NC];          // NHWC fp16
__device__ float g_E  [Bn*HW];
__device__ __half g_h2 [Bn*NC*HW];               // NHWC fp16
__device__ float g_ch [Bn*HW2];
__device__ float g_z  [Bn*NC*HW2];
__device__ float g_hcm[Bn*NC*130*130];
__device__ float g_xm [Bn*Dc*HW2];
__device__ float g_w5 [25*NC];
__device__ uint32_t g_bfrag[9*3*6*32*2];         // B fragments [tap][kc][nt][lane][2]
__device__ float g_red[276];
__device__ float g_sb [384];

__device__ const int c_dx[8] = {0,1,1,1,0,-1,-1,-1};
__device__ const int c_dy[8] = {1,1,0,-1,-1,-1,0,1};

// ---- streams/events created at program init ----
struct HXStreams {
    cudaStream_t s2;
    cudaEvent_t e1, e2;
    HXStreams() {
        cudaStreamCreateWithFlags(&s2, cudaStreamNonBlocking);
        cudaEventCreateWithFlags(&e1, cudaEventDisableTiming);
        cudaEventCreateWithFlags(&e2, cudaEventDisableTiming);
    }
};
static HXStreams g_hx;

// fast tanh (SASS TANH, single op) — R15 measured: rel_err unchanged vs exact
__device__ __forceinline__ float ftanh(float x) {
    float y;
    asm("tanh.approx.f32 %0, %1;" : "=f"(y) : "f"(x));
    return y;
}
__device__ __forceinline__ float fsig(float x) {
    return fmaf(0.5f, ftanh(0.5f*x), 0.5f);
}

// ---- packed f32x2 ----
__device__ __forceinline__ unsigned long long pack2(float a, float b) {
    unsigned long long r;
    asm("mov.b64 %0, {%1, %2};" : "=l"(r) : "f"(a), "f"(b));
    return r;
}
__device__ __forceinline__ void ffma2(unsigned long long &d, unsigned long long a,
                                      unsigned long long b) {
    asm("fma.rn.f32x2 %0, %1, %2, %0;" : "+l"(d) : "l"(a), "l"(b));
}
__device__ __forceinline__ float2 unpack2(unsigned long long v) {
    float2 f;
    asm("mov.b64 {%0, %1}, %2;" : "=f"(f.x), "=f"(f.y) : "l"(v));
    return f;
}

// ---- warp mma + ldmatrix ----
__device__ __forceinline__ void mma16816(float* d, const uint32_t* a, uint32_t b0, uint32_t b1) {
    asm volatile("mma.sync.aligned.m16n8k16.row.col.f32.f16.f16.f32 "
        "{%0,%1,%2,%3}, {%4,%5,%6,%7}, {%8,%9}, {%0,%1,%2,%3};"
        : "+f"(d[0]), "+f"(d[1]), "+f"(d[2]), "+f"(d[3])
        : "r"(a[0]), "r"(a[1]), "r"(a[2]), "r"(a[3]), "r"(b0), "r"(b1));
}
__device__ __forceinline__ void ldsm_x4(uint32_t* r, uint32_t addr) {
    asm volatile("ldmatrix.sync.aligned.m8n8.x4.shared.b16 {%0,%1,%2,%3}, [%4];"
        : "=r"(r[0]), "=r"(r[1]), "=r"(r[2]), "=r"(r[3]) : "r"(addr));
}
__device__ __forceinline__ uint32_t smem_u32(const void* p) {
    uint32_t a;
    asm("{ .reg .u64 t; cvta.to.shared.u64 t, %1; cvt.u32.u64 %0, t; }" : "=r"(a) : "l"(p));
    return a;
}

// smem layout of k_hmma_mdc1 (dynamic): A staging + reduction only (B frags via L1)
#define SM_IN  0
#define SM_RED 43680
#define SMEM_TOT (SM_RED + 384)

// ---------------- tiny kernels ----------------
__global__ void k_zero(float* red) { if (threadIdx.x < 276) red[threadIdx.x] = 0.f; }

__global__ void k_mom6(const float* __restrict__ x, float* __restrict__ out, int hw) {
    float S[6] = {0,0,0,0,0,0};
    float P[21];
    #pragma unroll
    for (int i = 0; i < 21; i++) P[i] = 0.f;
    int total = Bn*hw;
    for (int t = blockIdx.x*blockDim.x + threadIdx.x; t < total; t += gridDim.x*blockDim.x) {
        int b = t / hw, i = t - b*hw;
        const float* p = x + (long)b*6*hw + i;
        float v[6];
        #pragma unroll
        for (int d = 0; d < 6; d++) v[d] = p[(long)d*hw];
        int idx = 0;
        #pragma unroll
        for (int d = 0; d < 6; d++) {
            S[d] += v[d];
            #pragma unroll
            for (int e = d; e < 6; e++) { P[idx] += v[d]*v[e]; idx++; }
        }
    }
    #pragma unroll
    for (int o = 16; o > 0; o >>= 1) {
        #pragma unroll
        for (int d = 0; d < 6; d++)  S[d] += __shfl_down_sync(0xffffffffu, S[d], o);
        #pragma unroll
        for (int i = 0; i < 21; i++) P[i] += __shfl_down_sync(0xffffffffu, P[i], o);
    }
    if ((threadIdx.x & 31) == 0) {
        #pragma unroll
        for (int d = 0; d < 6; d++)  atomicAdd(&out[d], S[d]);
        #pragma unroll
        for (int i = 0; i < 21; i++) atomicAdd(&out[6+i], P[i]);
    }
}

__global__ void k_sb6(const float* __restrict__ mom, const float* __restrict__ w1,
                      const float* __restrict__ g, const float* __restrict__ bt,
                      float* __restrict__ sb, float invN) {
    int c = threadIdx.x;
    if (c >= NC) return;
    float m = 0.f;
    #pragma unroll
    for (int d = 0; d < 6; d++) m += w1[c*6+d]*mom[d];
    m *= invN;
    float q = 0.f; int idx = 0;
    #pragma unroll
    for (int d = 0; d < 6; d++)
        #pragma unroll
        for (int e = d; e < 6; e++) {
            float coef = (d == e) ? 1.f : 2.f;
            q += coef * w1[c*6+d]*w1[c*6+e]*mom[6+idx];
            idx++;
        }
    q *= invN;
    float var = q - m*m;
    float sc = g[c]*rsqrtf(var + 1e-5f);
    sb[c] = sc; sb[NC+c] = bt[c] - m*sc;
}

__global__ void k_bnsb(const float* __restrict__ sums, const float* __restrict__ g,
                       const float* __restrict__ bt, float* __restrict__ sb, float invN) {
    int c = threadIdx.x;
    if (c >= NC) return;
    float m = sums[c]*invN;
    float var = sums[NC+c]*invN - m*m;
    float sc = g[c]*rsqrtf(var + 1e-5f);
    sb[c] = sc; sb[NC+c] = bt[c] - m*sc;
}

__global__ void k_env(const float* __restrict__ x, const float* __restrict__ w1,
                      const float* __restrict__ w2, const float* __restrict__ sb,
                      float* __restrict__ E) {
    __shared__ float s_w1[288], s_w2[48], s_s[48], s_b[48];
    int t = threadIdx.x;
    for (int i = t; i < 288; i += 256) s_w1[i] = w1[i];
    if (t < 48) { s_w2[t] = w2[t]; s_s[t] = sb[t]; s_b[t] = sb[48+t]; }
    __syncthreads();
    int idx = blockIdx.x*256 + t;
    int b = idx >> 16, pix = idx & 65535;
    const float* xp = x + (long)b*6*HW + pix;
    float v[6];
    #pragma unroll
    for (int d = 0; d < 6; d++) v[d] = xp[(long)d*HW];
    float e = 0.f;
    #pragma unroll 4
    for (int c = 0; c < 48; c++) {
        float y = s_w1[c*6]*v[0];
        #pragma unroll
        for (int d = 1; d < 6; d++) y = fmaf(s_w1[c*6+d], v[d], y);
        e = fmaf(s_w2[c], ftanh(fmaf(s_s[c], y, s_b[c])), e);
    }
    E[idx] = e;
}

__global__ void k_w5(const float* __restrict__ md_ct, float* __restrict__ W5) {
    int oc = threadIdx.x;
    if (oc >= 48) return;
    float w5[25];
    #pragma unroll
    for (int i = 0; i < 25; i++) w5[i] = 0.f;
    for (int k = 0; k < 8; k++)
        for (int ky = 0; ky < 3; ky++)
            for (int kx = 0; kx < 3; kx++) {
                int u = ky - 2 + c_dy[k] + 3;
                int v = kx - 2 - c_dx[k] + 3;
                w5[u*5+v] += md_ct[oc*90 + (k+2)*9 + ky*3 + kx];
            }
    for (int i = 0; i < 25; i++) W5[i*48 + oc] = w5[i];
}

// md_c1 weights -> fp16 B fragments in mma register order
__global__ void k_wb(const float* __restrict__ md_c1, uint32_t* __restrict__ bfrag) {
    int i = blockIdx.x*256 + threadIdx.x;
    if (i >= 9*3*6*32*2) return;
    int r    = i & 1;
    int lane = (i >> 1) & 31;
    int nt   = (i >> 6) % 6;
    int kc   = (i / (64*6)) % 3;
    int tap  = i / (64*6*3);
    int n  = nt*8 + (lane >> 2);
    int k0 = (lane & 3)*2 + r*8;
    float w0 = md_c1[((n*48) + kc*16 + k0    )*9 + tap];
    float w1 = md_c1[((n*48) + kc*16 + k0 + 1)*9 + tap];
    __half2 pk;
    pk.x = __float2half_rn(w0);
    pk.y = __float2half_rn(w1);
    bfrag[i] = *(uint32_t*)&pk;
}

__device__ __forceinline__ void store_h2(__half* h1, long base, float v0, float v1) {
    __half2 p;
    p.x = __float2half_rn(v0);
    p.y = __float2half_rn(v1);
    *(uint32_t*)(h1 + base) = *(uint32_t*)&p;
}

// md_ct interior (FFMA2), outputs NHWC fp16
__global__ void __launch_bounds__(256, 2)
k_mdct(const float* __restrict__ x, const float* __restrict__ E,
       const float* __restrict__ W5, const float* __restrict__ md_ct,
       __half* __restrict__ h1) {
    __shared__ float sE[36*36];
    __shared__ float sx[2][34*34];
    __shared__ alignas(16) float s_w5[25*16];
    __shared__ alignas(16) float s_w3[2*9*16];
    int tid = threadIdx.x;
    int oc_base = blockIdx.x * 16;
    int b = blockIdx.z;
    int tX = blockIdx.y & 7, tY = blockIdx.y >> 3;
    int p0 = 2 + tY*32, q0 = 2 + tX*32;

    for (int i = tid; i < 25*16; i += 256) {
        int tap = i >> 4, o = i & 15;
        s_w5[i] = W5[tap*48 + oc_base + o];
    }
    for (int i = tid; i < 288; i += 256) {
        int o = i & 15, rest = i >> 4;
        s_w3[i] = md_ct[(oc_base + o)*90 + rest];
    }
    for (int i = tid; i < 1296; i += 256) {
        int lr = i / 36, lc = i - lr*36;
        int gy = (p0 - 3 + lr) & 255, gx = (q0 - 3 + lc) & 255;
        sE[i] = E[b*HW + (gy << 8) + gx];
    }
    #pragma unroll
    for (int ch = 0; ch < 2; ch++)
        for (int i = tid; i < 1156; i += 256) {
            int lr = i / 34, lc = i - lr*34;
            int gy = p0 - 2 + lr, gx = q0 - 2 + lc;
            float v = 0.f;
            if (gy < 256 && gx < 256) v = x[((long)b*6 + ch)*HW + (gy << 8) + gx];
            sx[ch][i] = v;
        }
    __syncthreads();

    int tx = tid & 31, ty = tid >> 5;
    unsigned long long acc2[4][8];
    #pragma unroll
    for (int p = 0; p < 4; p++)
        #pragma unroll
        for (int j = 0; j < 8; j++) acc2[p][j] = 0ull;

    #pragma unroll
    for (int u = 0; u < 5; u++) {
        float v[4][5];
        #pragma unroll
        for (int p = 0; p < 4; p++) {
            int base = (ty + 8*p + u)*36 + tx;
            #pragma unroll
            for (int j = 0; j < 5; j++) v[p][j] = sE[base + j];
        }
        #pragma unroll
        for (int vv = 0; vv < 5; vv++) {
            unsigned long long v2[4];
            #pragma unroll
            for (int p = 0; p < 4; p++) v2[p] = pack2(v[p][vv], v[p][vv]);
            const float4* w4 = (const float4*)&s_w5[(u*5 + vv)*16];
            #pragma unroll
            for (int q = 0; q < 4; q++) {
                float4 t4 = w4[q];
                unsigned long long wA = pack2(t4.x, t4.y), wB = pack2(t4.z, t4.w);
                #pragma unroll
                for (int p = 0; p < 4; p++) {
                    ffma2(acc2[p][q*2],   v2[p], wA);
                    ffma2(acc2[p][q*2+1], v2[p], wB);
                }
            }
        }
    }
    #pragma unroll
    for (int ch = 0; ch < 2; ch++)
        #pragma unroll
        for (int ky = 0; ky < 3; ky++) {
            float v[4][3];
            #pragma unroll
            for (int p = 0; p < 4; p++) {
                int base = (ty + 8*p + ky)*34 + tx;
                v[p][0] = sx[ch][base]; v[p][1] = sx[ch][base+1]; v[p][2] = sx[ch][base+2];
            }
            #pragma unroll
            for (int kx = 0; kx < 3; kx++) {
                unsigned long long v2[4];
                #pragma unroll
                for (int p = 0; p < 4; p++) v2[p] = pack2(v[p][kx], v[p][kx]);
                const float4* w4 = (const float4*)&s_w3[(ch*9 + ky*3 + kx)*16];
                #pragma unroll
                for (int q = 0; q < 4; q++) {
                    float4 t4 = w4[q];
                    unsigned long long wA = pack2(t4.x, t4.y), wB = pack2(t4.z, t4.w);
                    #pragma unroll
                    for (int p = 0; p < 4; p++) {
                        ffma2(acc2[p][q*2],   v2[p], wA);
                        ffma2(acc2[p][q*2+1], v2[p], wB);
                    }
                }
            }
        }

    #pragma unroll
    for (int p = 0; p < 4; p++) {
        int pp = p0 + ty + 8*p, qq = q0 + tx;
        if (pp <= 255 && qq <= 255) {
            long base = ((long)(b*258 + pp)*258 + qq)*48 + oc_base;
            #pragma unroll
            for (int j = 0; j < 8; j++) {
                float2 f = unpack2(acc2[p][j]);
                store_h2(h1, base + 2*j, ftanh(f.x), ftanh(f.y));
            }
        }
    }
}

// md_ct boundary
__global__ void k_mdct_edge(const float* __restrict__ x, const float* __restrict__ E,
                            const float* __restrict__ md_ct, __half* __restrict__ h1) {
    __shared__ float s_w[4320];
    int tid = threadIdx.x;
    for (int i = tid; i < 4320; i += 256) {
        int oc = i % 48, rest = i / 48;
        s_w[rest*48 + oc] = md_ct[oc*90 + rest];
    }
    __syncthreads();
    int idx = blockIdx.x*256 + tid;
    int b = blockIdx.y;
    int p, q;
    if (idx < 1032) { int r = idx/258; p = (r < 2) ? r : 254 + r; q = idx - r*258; }
    else { int j = idx - 1032; int c = j/254; q = (c < 2) ? c : 254 + c; p = 2 + (j - c*254); }
    float acc[48];
    #pragma unroll
    for (int o = 0; o < 48; o++) acc[o] = 0.f;
    for (int ch = 0; ch < 10; ch++)
        for (int ky = 0; ky < 3; ky++)
            for (int kx = 0; kx < 3; kx++) {
                int y = p - 2 + ky, xx = q - 2 + kx;
                if ((unsigned)y < 256u && (unsigned)xx < 256u) {
                    float v;
                    if (ch < 2) v = x[((long)b*6 + ch)*HW + (y << 8) + xx];
                    else {
                        int k = ch - 2;
                        v = E[b*HW + (((y + c_dy[k]) & 255) << 8) + ((xx - c_dx[k]) & 255)];
                    }
                    const float* wr = &s_w[(ch*9 + ky*3 + kx)*48];
                    #pragma unroll
                    for (int o = 0; o < 48; o++) acc[o] = fmaf(v, wr[o], acc[o]);
                }
            }
    long base = ((long)(b*258 + p)*258 + q)*48;
    #pragma unroll
    for (int o = 0; o < 48; o += 2)
        store_h2(h1, base + o, ftanh(acc[o]), ftanh(acc[o+1]));
}

// ---------------- md_c1 via warp fp16 mma (ldmatrix A, B frags from L1) ----------------
__global__ void __launch_bounds__(256, 3)
k_hmma_mdc1(const __half* __restrict__ h1, const uint32_t* __restrict__ bfrag,
            __half* __restrict__ h2, float* __restrict__ red) {
    extern __shared__ char smem[];
    uint32_t* sA  = (uint32_t*)(smem + SM_IN);
    float* s_red  = (float*)(smem + SM_RED);
    uint32_t sA_addr = smem_u32(smem) + SM_IN;

    int tid = threadIdx.x, wid = tid >> 5, lane = tid & 31;
    int wm = wid >> 1, wn = wid & 1;
    int g = lane >> 2, tg = lane & 3;
    int m0 = wm * 32;
    uint32_t roff = (uint32_t)(((lane & 15)*28 + (lane >> 4)*4) * 4);
    const uint2* bf = (const uint2*)bfrag + lane;

    if (tid < 96) s_red[tid] = 0.f;

    for (int t = 0; t < 4; t++) {
        int gt = blockIdx.x*4 + t;
        int hf = gt & 1, p = (gt >> 1) & 255, b = gt >> 9;
        int q0 = hf << 7;

        __syncthreads();
        const uint4* srcA = (const uint4*)(h1 + ((long)(b*258 + p)*258 + q0)*48);
        uint4* dstA = (uint4*)sA;
        for (int i = tid; i < 3*130*6; i += 256) {
            int px = i / 6, w4 = i - px*6;
            int ky = px / 130, lp = px - ky*130;
            dstA[px*7 + w4] = srcA[(long)ky*(258*6) + lp*6 + w4];
        }
        __syncthreads();

        float acc[2][3][4];
        #pragma unroll
        for (int mt = 0; mt < 2; mt++)
            #pragma unroll
            for (int nt = 0; nt < 3; nt++)
                #pragma unroll
                for (int r = 0; r < 4; r++) acc[mt][nt][r] = 0.f;

        #pragma unroll 1
        for (int tap = 0; tap < 9; tap++) {
            int ky = tap/3, kx = tap - ky*3;
            int rowbase = ky*130 + m0 + kx;
            #pragma unroll
            for (int kc = 0; kc < 3; kc++) {
                const uint2* bp = bf + ((tap*3 + kc)*6 + wn*3)*32;
                uint2 b0 = __ldg(bp);
                uint2 b1 = __ldg(bp + 32);
                uint2 b2 = __ldg(bp + 64);
                uint32_t ah[2][4];
                #pragma unroll
                for (int mt = 0; mt < 2; mt++) {
                    uint32_t addr = sA_addr + (uint32_t)((rowbase + mt*16)*112 + kc*32) + roff;
                    ldsm_x4(ah[mt], addr);
                }
                #pragma unroll
                for (int mt = 0; mt < 2; mt++) {
                    mma16816(acc[mt][0], ah[mt], b0.x, b0.y);
                    mma16816(acc[mt][1], ah[mt], b1.x, b1.y);
                    mma16816(acc[mt][2], ah[mt], b2.x, b2.y);
                }
            }
        }

        float csum[3][2], csq[3][2];
        #pragma unroll
        for (int ntl = 0; ntl < 3; ntl++) { csum[ntl][0]=0.f; csum[ntl][1]=0.f; csq[ntl][0]=0.f; csq[ntl][1]=0.f; }
        #pragma unroll
        for (int mt = 0; mt < 2; mt++) {
            int pr0 = q0 + m0 + mt*16 + g;
            __half* o0 = h2 + ((long)((b*256 + p)*256) + pr0)*48 + wn*24;
            __half* o1 = o0 + 8*48;
            #pragma unroll
            for (int ntl = 0; ntl < 3; ntl++) {
                float v0 = ftanh(acc[mt][ntl][0]);
                float v1 = ftanh(acc[mt][ntl][1]);
                float v2 = ftanh(acc[mt][ntl][2]);
                float v3 = ftanh(acc[mt][ntl][3]);
                int co = ntl*8 + tg*2;
                *(__half2*)(o0 + co) = __floats2half2_rn(v0, v1);
                *(__half2*)(o1 + co) = __floats2half2_rn(v2, v3);
                csum[ntl][0] += v0 + v2; csum[ntl][1] += v1 + v3;
                csq[ntl][0]  += v0*v0 + v2*v2; csq[ntl][1] += v1*v1 + v3*v3;
            }
        }
        #pragma unroll
        for (int ntl = 0; ntl < 3; ntl++)
            #pragma unroll
            for (int c2 = 0; c2 < 2; c2++) {
                float s = csum[ntl][c2], q = csq[ntl][c2];
                #pragma unroll
                for (int o = 16; o >= 4; o >>= 1) {
                    s += __shfl_down_sync(0xffffffffu, s, o);
                    q += __shfl_down_sync(0xffffffffu, q, o);
                }
                if (g == 0) {
                    int col = wn*24 + ntl*8 + tg*2 + c2;
                    atomicAdd(&s_red[col], s);
                    atomicAdd(&s_red[48 + col], q);
                }
            }
    }
    __syncthreads();
    for (int i = tid; i < 96; i += 256) atomicAdd(&red[i], s_red[i]);
}

// ---------------- direct 3x3 conv (FFMA2) — cm_ct / cm_c2 ----------------
template<int CIN_G, int OCB, int PAD, bool DOTANH, bool SAFE, bool PREBN>
__global__ void __launch_bounds__(256, 2)
k_conv3(const float* __restrict__ in, const float* __restrict__ wgt,
        const float* __restrict__ sbp, float* __restrict__ out,
        int H_in, int W_in, int H_out, int W_out, int C_in, int C_out, int tilesX) {
    __shared__ float s_tile[34*34];
    __shared__ alignas(16) float s_w[CIN_G*9*OCB];
    __shared__ float s_sc[CIN_G], s_bi[CIN_G];

    int tid = threadIdx.x;
    int oc_base = blockIdx.x * OCB;
    int groups = C_in / CIN_G;
    int oc_per_group = C_out / groups;
    int ic_base = (oc_base / oc_per_group) * CIN_G;

    for (int i = tid; i < CIN_G*9*OCB; i += 256) {
        int o = i % OCB, rest = i / OCB;
        s_w[i] = wgt[(long)(oc_base + o)*(CIN_G*9) + rest];
    }
    if (PREBN && tid < CIN_G) { s_sc[tid] = sbp[ic_base + tid]; s_bi[tid] = sbp[48 + ic_base + tid]; }

    int tX = blockIdx.y % tilesX, tY = blockIdx.y / tilesX;
    int ox0 = tX*32, oy0 = tY*32;
    int tx = tid & 31, ty = tid >> 5;

    int off[5]; bool vld[5];
    #pragma unroll
    for (int s = 0; s < 5; s++) {
        int j = tid + s*256;
        int ly = j / 34, lx = j - ly*34;
        int gy = oy0 - PAD + ly, gx = ox0 - PAD + lx;
        bool v = (j < 1156);
        if (SAFE) v = v && ((unsigned)gy < (unsigned)H_in) && ((unsigned)gx < (unsigned)W_in);
        vld[s] = v;
        off[s] = gy*W_in + gx;
    }

    const float* inb = in + ((long)blockIdx.z * C_in + ic_base) * H_in * W_in;
    float r[5];
    #pragma unroll
    for (int s = 0; s < 5; s++) r[s] = vld[s] ? __ldg(inb + off[s]) : 0.f;

    unsigned long long acc2[4][OCB/2];
    #pragma unroll
    for (int p = 0; p < 4; p++)
        #pragma unroll
        for (int j = 0; j < OCB/2; j++) acc2[p][j] = 0ull;

    __syncthreads();

    #pragma unroll 1
    for (int ic = 0; ic < CIN_G; ic++) {
        float sc = 0.f, bi = 0.f;
        if (PREBN) { sc = s_sc[ic]; bi = s_bi[ic]; }
        #pragma unroll
        for (int s = 0; s < 5; s++) {
            int j = tid + s*256;
            if (j < 1156) {
                float v = r[s];
                if (PREBN) v = ftanh(fmaf(sc, v, bi));
                s_tile[j] = v;
            }
        }
        __syncthreads();
        if (ic + 1 < CIN_G) {
            const float* src = inb + (long)(ic+1)*H_in*W_in;
            #pragma unroll
            for (int s = 0; s < 5; s++) r[s] = vld[s] ? __ldg(src + off[s]) : 0.f;
        }
        const float* wic = &s_w[ic*9*OCB];
        #pragma unroll
        for (int ky = 0; ky < 3; ky++) {
            float v[4][3];
            #pragma unroll
            for (int p = 0; p < 4; p++) {
                int base = (ty + 8*p + ky)*34 + tx;
                v[p][0] = s_tile[base]; v[p][1] = s_tile[base+1]; v[p][2] = s_tile[base+2];
            }
            #pragma unroll
            for (int kx = 0; kx < 3; kx++) {
                unsigned long long v2[4];
                #pragma unroll
                for (int p = 0; p < 4; p++) v2[p] = pack2(v[p][kx], v[p][kx]);
                if (OCB % 4 == 0) {
                    const float4* w4 = (const float4*)&wic[(ky*3 + kx)*OCB];
                    #pragma unroll
                    for (int q = 0; q < OCB/4; q++) {
                        float4 t4 = w4[q];
                        unsigned long long wA = pack2(t4.x, t4.y), wB = pack2(t4.z, t4.w);
                        #pragma unroll
                        for (int p = 0; p < 4; p++) {
                            ffma2(acc2[p][q*2],   v2[p], wA);
                            ffma2(acc2[p][q*2+1], v2[p], wB);
                        }
                    }
                } else {
                    #pragma unroll
                    for (int j = 0; j < OCB/2; j++) {
                        unsigned long long ww =
                            *(const unsigned long long*)&wic[(ky*3 + kx)*OCB + 2*j];
                        #pragma unroll
                        for (int p = 0; p < 4; p++) ffma2(acc2[p][j], v2[p], ww);
                    }
                }
            }
        }
        __syncthreads();
    }

    #pragma unroll
    for (int p = 0; p < 4; p++) {
        int oy = oy0 + ty + 8*p, ox = ox0 + tx;
        bool ok = (oy < H_out) && (ox < W_out);
        float* op = out + (((long)blockIdx.z*C_out + oc_base)*H_out + oy)*W_out + ox;
        long cs = (long)H_out*W_out;
        #pragma unroll
        for (int j = 0; j < OCB/2; j++) {
            float2 f = unpack2(acc2[p][j]);
            float v0 = DOTANH ? ftanh(f.x) : f.x;
            float v1 = DOTANH ? ftanh(f.y) : f.y;
            if (ok) { op[(2*j)*cs] = v0; op[(2*j+1)*cs] = v1; }
        }
    }
}

// CHANGE (h2 NHWC fp16) — float4 loads (8 ch/load), fast tanh
__global__ void k_change(const __half* __restrict__ h2, const float* __restrict__ sb,
                         const float* __restrict__ w2, float* __restrict__ ch) {
    __shared__ float s_s[48], s_b[48], s_w[192];
    int t = threadIdx.x;
    if (t < 48) { s_s[t] = sb[t]; s_b[t] = sb[48+t]; }
    if (t < 192) s_w[t] = w2[t];
    __syncthreads();
    int idx = blockIdx.x*256 + t;
    int b = idx >> 14, pix = idx & 16383;
    int i = pix >> 7, j = pix & 127;
    const float4* q00 = (const float4*)(h2 + ((long)((b*256 + 2*i)*256) + 2*j)*48);
    const float4* q01 = q00 + 6;
    const float4* q10 = q00 + 256*6;
    const float4* q11 = q10 + 6;
    float a = 0.f;
    #pragma unroll
    for (int c8 = 0; c8 < 6; c8++) {
        float4 r0 = q00[c8], r1 = q01[c8], r2 = q10[c8], r3 = q11[c8];
        const __half2* h0 = (const __half2*)&r0;
        const __half2* h1v = (const __half2*)&r1;
        const __half2* h2v = (const __half2*)&r2;
        const __half2* h3 = (const __half2*)&r3;
        #pragma unroll
        for (int k2 = 0; k2 < 4; k2++) {
            int c = c8*8 + k2*2;
            float2 v0 = __half22float2(h0[k2]);
            float2 v1 = __half22float2(h1v[k2]);
            float2 v2 = __half22float2(h2v[k2]);
            float2 v3 = __half22float2(h3[k2]);
            float s0 = s_s[c], b0 = s_b[c], s1 = s_s[c+1], b1 = s_b[c+1];
            a = fmaf(ftanh(fmaf(s0, v0.x, b0)), s_w[c*4+0],     a);
            a = fmaf(ftanh(fmaf(s1, v0.y, b1)), s_w[(c+1)*4+0], a);
            a = fmaf(ftanh(fmaf(s0, v1.x, b0)), s_w[c*4+1],     a);
            a = fmaf(ftanh(fmaf(s1, v1.y, b1)), s_w[(c+1)*4+1], a);
            a = fmaf(ftanh(fmaf(s0, v2.x, b0)), s_w[c*4+2],     a);
            a = fmaf(ftanh(fmaf(s1, v2.y, b1)), s_w[(c+1)*4+2], a);
            a = fmaf(ftanh(fmaf(s0, v3.x, b0)), s_w[c*4+3],     a);
            a = fmaf(ftanh(fmaf(s1, v3.y, b1)), s_w[(c+1)*4+3], a);
        }
    }
    ch[idx] = fsig(a);
}

// cm conv1 (2x2 s2 g3) — 2 outputs/thread via float4 loads, fused reduction
__global__ void k_cm1red(const float* __restrict__ x, const float* __restrict__ w,
                         float* __restrict__ z, float* __restrict__ red) {
    __shared__ float ss[8], sq[8];
    int tid = threadIdx.x;
    int idx = blockIdx.x*256 + tid;
    int b = idx / (48*8192); int r = idx - b*48*8192;
    int oc = r >> 13; int unit = r & 8191;
    int i = unit >> 6, u = unit & 63;
    int g = oc >> 4;
    const float* xp = x + ((long)b*6 + 2*g)*HW + (2*i)*256 + 4*u;
    const float* wp = w + oc*8;
    float4 a0 = *(const float4*)xp;
    float4 a1 = *(const float4*)(xp + 256);
    float4 b0 = *(const float4*)(xp + HW);
    float4 b1 = *(const float4*)(xp + HW + 256);
    float o0 = wp[0]*a0.x + wp[1]*a0.y + wp[2]*a1.x + wp[3]*a1.y
             + wp[4]*b0.x + wp[5]*b0.y + wp[6]*b1.x + wp[7]*b1.y;
    float o1 = wp[0]*a0.z + wp[1]*a0.w + wp[2]*a1.z + wp[3]*a1.w
             + wp[4]*b0.z + wp[5]*b0.w + wp[6]*b1.z + wp[7]*b1.w;
    *(float2*)(z + (long)idx*2) = make_float2(o0, o1);
    float s = o0 + o1, q = o0*o0 + o1*o1;
    #pragma unroll
    for (int d = 16; d > 0; d >>= 1) {
        s += __shfl_down_sync(0xffffffffu, s, d);
        q += __shfl_down_sync(0xffffffffu, q, d);
    }
    int warp = tid >> 5, lane = tid & 31;
    if (lane == 0) { ss[warp] = s; sq[warp] = q; }
    __syncthreads();
    if (tid == 0) {
        float S = 0.f, Q = 0.f;
        #pragma unroll
        for (int w8 = 0; w8 < 8; w8++) { S += ss[w8]; Q += sq[w8]; }
        atomicAdd(&red[oc], S); atomicAdd(&red[48 + oc], Q);
    }
}

__global__ void k_final(const float* __restrict__ xm, const float* __restrict__ ch,
                        const float* __restrict__ w1, const float* __restrict__ w2,
                        const float* __restrict__ sb, float* __restrict__ out) {
    __shared__ float s_w1[288], s_w2[288], s_s[48], s_b[48];
    int t = threadIdx.x;
    for (int i = t; i < 288; i += 256) { s_w1[i] = w1[i]; s_w2[i] = w2[i]; }
    if (t < 48)  { s_s[t] = sb[t]; s_b[t] = sb[48+t]; }
    __syncthreads();
    int idx = blockIdx.x*256 + t;
    int b = idx >> 14, pix = idx & 16383;
    const float* xp = xm + ((long)b*6)*HW2 + pix;
    float v[6];
    #pragma unroll
    for (int d = 0; d < 6; d++) v[d] = xp[d*HW2];
    float born[6] = {0,0,0,0,0,0};
    #pragma unroll 4
    for (int c = 0; c < 48; c++) {
        float y = s_w1[c*6]*v[0];
        #pragma unroll
        for (int d = 1; d < 6; d++) y = fmaf(s_w1[c*6+d], v[d], y);
        float h = ftanh(fmaf(s_s[c], y, s_b[c]));
        #pragma unroll
        for (int d = 0; d < 6; d++) born[d] = fmaf(s_w2[d*48+c], h, born[d]);
    }
    float cc = ch[idx];
    #pragma unroll
    for (int d = 0; d < 6; d++) {
        float o = v[d]*(1.f - cc) + cc*born[d];
        if (d < 3) o = fsig(o);
        out[((long)b*6 + d)*HW2 + pix] = o;
    }
}

// ---------------- launch (R12 structure) ----------------
extern "C" void kernel_launch(void* const* d_in, const int* in_sizes, int n_in,
                              void* d_out, int out_size) {
    const float* x     = (const float*)d_in[0];
    const float* ce_w1 = (const float*)d_in[1];
    const float* ce_g  = (const float*)d_in[2];
    const float* ce_b  = (const float*)d_in[3];
    const float* ce_w2 = (const float*)d_in[4];
    const float* md_ct = (const float*)d_in[5];
    const float* md_c1 = (const float*)d_in[6];
    const float* md_g  = (const float*)d_in[7];
    const float* md_b  = (const float*)d_in[8];
    const float* md_c2 = (const float*)d_in[9];
    const float* cm_w1 = (const float*)d_in[10];
    const float* cm_g  = (const float*)d_in[11];
    const float* cm_b  = (const float*)d_in[12];
    const float* cm_ct = (const float*)d_in[13];
    const float* cm_c2 = (const float*)d_in[14];
    const float* bo_w1 = (const float*)d_in[15];
    const float* bo_g  = (const float*)d_in[16];
    const float* bo_b  = (const float*)d_in[17];
    const float* bo_w2 = (const float*)d_in[18];

    float *E, *ch, *z, *hcm, *xm, *w5, *red, *sb;
    __half *h1, *h2;
    uint32_t *bfrag;
    cudaGetSymbolAddress((void**)&E,     g_E);
    cudaGetSymbolAddress((void**)&h1,    g_h1);
    cudaGetSymbolAddress((void**)&h2,    g_h2);
    cudaGetSymbolAddress((void**)&ch,    g_ch);
    cudaGetSymbolAddress((void**)&z,     g_z);
    cudaGetSymbolAddress((void**)&hcm,   g_hcm);
    cudaGetSymbolAddress((void**)&xm,    g_xm);
    cudaGetSymbolAddress((void**)&w5,    g_w5);
    cudaGetSymbolAddress((void**)&red,   g_red);
    cudaGetSymbolAddress((void**)&sb,    g_sb);
    cudaGetSymbolAddress((void**)&bfrag, g_bfrag);

    cudaFuncSetAttribute(k_hmma_mdc1, cudaFuncAttributeMaxDynamicSharedMemorySize, SMEM_TOT);

    const float invN_full = 1.f/(float)(Bn*HW);
    const float invN_half = 1.f/(float)(Bn*HW2);

    k_zero<<<1, 512>>>(red);

    // ---- fork: cell-merge chain on s2 ----
    cudaEventRecord(g_hx.e1, 0);
    cudaStreamWaitEvent(g_hx.s2, g_hx.e1, 0);

    k_cm1red<<<Bn*48*8192/256, 256, 0, g_hx.s2>>>(x, cm_w1, z, red + 138);
    k_bnsb<<<1, 64, 0, g_hx.s2>>>(red + 138, cm_g, cm_b, sb + 192, invN_half);
    k_conv3<16, 16, 2, true, true, true>
        <<<dim3(3, 25, Bn), 256, 0, g_hx.s2>>>(z, cm_ct, sb + 192, hcm,
                                               128, 128, 130, 130, 48, 48, 5);
    k_conv3<16, 2, 0, true, false, false>
        <<<dim3(3, 16, Bn), 256, 0, g_hx.s2>>>(hcm, cm_c2, nullptr, xm,
                                               130, 130, 128, 128, 48, 6, 4);
    k_mom6<<<64, 256, 0, g_hx.s2>>>(xm, red + 234, HW2);
    k_sb6 <<<1, 64, 0, g_hx.s2>>>(red + 234, bo_w1, bo_g, bo_b, sb + 288, invN_half);
    cudaEventRecord(g_hx.e2, g_hx.s2);

    // ---- md chain on default stream ----
    k_mom6<<<64, 256>>>(x, red + 0, HW);
    k_sb6 <<<1, 64>>>(red + 0, ce_w1, ce_g, ce_b, sb + 0, invN_full);
    k_env <<<Bn*HW/256, 256>>>(x, ce_w1, ce_w2, sb + 0, E);
    k_w5<<<1, 64>>>(md_ct, w5);
    k_wb<<<41, 256>>>(md_c1, bfrag);
    k_mdct<<<dim3(3, 64, Bn), 256>>>(x, E, w5, md_ct, h1);
    k_mdct_edge<<<dim3(8, Bn), 256>>>(x, E, md_ct, h1);
    k_hmma_mdc1<<<1024, 256, SMEM_TOT>>>(h1, bfrag, h2, red + 42);
    k_bnsb<<<1, 64>>>(red + 42, md_g, md_b, sb + 96, invN_full);
    k_change<<<Bn*HW2/256, 256>>>(h2, sb + 96, md_c2, ch);

    // ---- join, then final blend ----
    cudaStreamWaitEvent(0, g_hx.e2, 0);
    k_final<<<Bn*HW2/256, 256>>>(xm, ch, bo_w1, bo_w2, sb + 288, (float*)d_out);
}